// round 9
// baseline (speedup 1.0000x reference)
#include <cuda_runtime.h>
#include <stdint.h>
#include <math.h>

#define Bdim 4
#define Nseq 2048
#define Ddim 1024
#define FFd  4096
#define Ttok 8192
#define ETA_C 0.1f
#define DT_C  0.01f

// ---------------- scratch ----------------
__device__ float g_V[Ttok];
__device__ float g_gamma[Ttok];
__device__ float g_a[Ttok * 2];
__device__ float g_bcf[Ttok * 2];
__device__ float g_x1[(size_t)Ttok * Ddim];
__device__ float g_xn2[(size_t)Ttok * Ddim];
__device__ float g_qkv[(size_t)Ttok * 1536];
__device__ float g_Qs[(size_t)Ttok * 512];
__device__ float g_Oin[(size_t)Ttok * 512];
__device__ float g_heb[(size_t)Ttok * 512];
__device__ float g_U[32 * 32 * 4096];
__device__ float g_Wst[32 * 32 * 4096];
__device__ float g_Pl[32 * 32];
__device__ float g_x2[(size_t)Ttok * Ddim];
__device__ float g_xn3[(size_t)Ttok * Ddim];
__device__ float g_ff[(size_t)Ttok * FFd];

// ---------------- helpers ----------------
__device__ __forceinline__ float blk_sum256(float v, float* sh) {
    int t = threadIdx.x;
#pragma unroll
    for (int o = 16; o > 0; o >>= 1) v += __shfl_down_sync(0xffffffffu, v, o);
    if ((t & 31) == 0) sh[t >> 5] = v;
    __syncthreads();
    if (t < 32) {
        float r = (t < 8) ? sh[t] : 0.f;
#pragma unroll
        for (int o = 4; o > 0; o >>= 1) r += __shfl_down_sync(0xffffffffu, r, o);
        if (t == 0) sh[0] = r;
    }
    __syncthreads();
    float r = sh[0];
    __syncthreads();
    return r;
}

__device__ __forceinline__ float gelu_f(float x) {
    float x3 = x * x * x;
    float u = 0.7978845608028654f * (x + 0.044715f * x3);
    return 0.5f * x * (1.f + tanhf(u));
}

// ---------------- K1: LN1 + potential projection ----------------
__global__ void ln1_pot_kernel(const float* __restrict__ x, const float* __restrict__ g1,
                               const float* __restrict__ b1, const float* __restrict__ wpot,
                               const float* __restrict__ bpot) {
    int row = blockIdx.x;
    int t = threadIdx.x;
    __shared__ float sh[8];
    const float4* xr = (const float4*)(x + (size_t)row * Ddim);
    float4 xv = xr[t];
    float s = xv.x + xv.y + xv.z + xv.w;
    float ss = xv.x * xv.x + xv.y * xv.y + xv.z * xv.z + xv.w * xv.w;
    s = blk_sum256(s, sh);
    ss = blk_sum256(ss, sh);
    float m = s * (1.f / Ddim);
    float var = ss * (1.f / Ddim) - m * m;
    float rstd = rsqrtf(var + 1e-5f);
    float xa[4] = {xv.x, xv.y, xv.z, xv.w};
    float p0 = 0.f, p1 = 0.f;
#pragma unroll
    for (int j = 0; j < 4; j++) {
        int col = t * 4 + j;
        float xn = (xa[j] - m) * rstd * g1[col] + b1[col];
        p0 += xn * wpot[col * 2];
        p1 += xn * wpot[col * 2 + 1];
    }
    p0 = blk_sum256(p0, sh);
    p1 = blk_sum256(p1, sh);
    if (t == 0) {
        g_V[row] = p0 + bpot[0];
        float z = p1 + bpot[1];
        float sp = (z > 20.f) ? z : log1pf(expf(z));
        g_gamma[row] = sp + 0.1f;
    }
}

// ---------------- K2: continued-fraction scans ----------------
__global__ void bk_scan_kernel() {
    int bb = blockIdx.x >> 1;
    int dir = blockIdx.x & 1;
    __shared__ float dre[128], dii[128], ore[128], oim[128];
    int t = threadIdx.x;
    float pre = 0.f, pim = 0.f;
    float* out = dir ? g_bcf : g_a;
    for (int c = 0; c < 16; c++) {
        int j = c * 128 + t;
        int pos = dir ? (Nseq - 1 - j) : j;
        int gi = bb * Nseq + pos;
        dre[t] = g_V[gi] + 2.f;
        dii[t] = -g_gamma[gi];
        __syncthreads();
        if (t == 0) {
            for (int u = 0; u < 128; u++) {
                float ar, ai;
                if (c == 0 && u == 0) {
                    ar = dre[0]; ai = dii[0];
                } else {
                    float inv = 1.f / (pre * pre + pim * pim);
                    ar = dre[u] - pre * inv;
                    ai = dii[u] + pim * inv;
                }
                ore[u] = ar; oim[u] = ai;
                pre = ar; pim = ai;
            }
        }
        __syncthreads();
        out[gi * 2] = ore[t];
        out[gi * 2 + 1] = oim[t];
        __syncthreads();
    }
}

// ---------------- K3: BK combine + residual + LN2 ----------------
__global__ void bk_res_ln2_kernel(const float* __restrict__ x, const float* __restrict__ wbk,
                                  const float* __restrict__ bbk, const float* __restrict__ g2,
                                  const float* __restrict__ b2) {
    int row = blockIdx.x;
    int t = threadIdx.x;
    __shared__ float sh[8];
    __shared__ float f01[2];
    if (t == 0) {
        float are = g_a[row * 2], aim = g_a[row * 2 + 1];
        float bre = g_bcf[row * 2], bim = g_bcf[row * 2 + 1];
        float dr = g_V[row] + 2.f, di = -g_gamma[row];
        float nr = are + bre - dr, ni = aim + bim - di;
        float inv = 1.f / (nr * nr + ni * ni);
        f01[0] = nr * inv;
        f01[1] = -ni * inv;
    }
    __syncthreads();
    float f0 = f01[0], f1 = f01[1];
    size_t base = (size_t)row * Ddim;
    float y[4];
    float s = 0.f, ss = 0.f;
#pragma unroll
    for (int j = 0; j < 4; j++) {
        int col = t * 4 + j;
        float v = x[base + col] + f0 * wbk[col] + f1 * wbk[Ddim + col] + bbk[col];
        y[j] = v;
        s += v;
        ss += v * v;
        g_x1[base + col] = v;
    }
    s = blk_sum256(s, sh);
    ss = blk_sum256(ss, sh);
    float m = s * (1.f / Ddim);
    float var = ss * (1.f / Ddim) - m * m;
    float rstd = rsqrtf(var + 1e-5f);
#pragma unroll
    for (int j = 0; j < 4; j++) {
        int col = t * 4 + j;
        g_xn2[base + col] = (y[j] - m) * rstd * g2[col] + b2[col];
    }
}

// ---------------- LN3 ----------------
__global__ void ln3_kernel(const float* __restrict__ g3, const float* __restrict__ b3) {
    int row = blockIdx.x;
    int t = threadIdx.x;
    __shared__ float sh[8];
    size_t base = (size_t)row * Ddim;
    float4 xv = *(const float4*)&g_x2[base + t * 4];
    float s = xv.x + xv.y + xv.z + xv.w;
    float ss = xv.x * xv.x + xv.y * xv.y + xv.z * xv.z + xv.w * xv.w;
    s = blk_sum256(s, sh);
    ss = blk_sum256(ss, sh);
    float m = s * (1.f / Ddim);
    float var = ss * (1.f / Ddim) - m * m;
    float rstd = rsqrtf(var + 1e-5f);
    float xa[4] = {xv.x, xv.y, xv.z, xv.w};
#pragma unroll
    for (int j = 0; j < 4; j++) {
        int col = t * 4 + j;
        g_xn3[base + col] = (xa[j] - m) * rstd * g3[col] + b3[col];
    }
}

// ---------------- TF32 GEMM: 128x256 block, 16 warps (2x8 of 64x32), 3-stage ----------------
#define AST 20             // A smem row stride (floats)
#define BST 260            // B smem row stride (floats)
#define ASZ (128 * AST)    // 2560
#define BSZ (16 * BST)     // 4160
#define SSZ (ASZ + BSZ)    // 6720 floats per stage
#define GSMEM (3 * SSZ * 4)

__device__ __forceinline__ void cpa16(unsigned dst, const void* src) {
    asm volatile("cp.async.ca.shared.global [%0], [%1], 16;\n" ::"r"(dst), "l"(src));
}
__device__ __forceinline__ unsigned f2tf32(float f) {
    unsigned u;
    asm("cvt.rna.tf32.f32 %0, %1;\n" : "=r"(u) : "f"(f));
    return u;
}

template <int EPI>
__global__ __launch_bounds__(512, 1) void tf32_gemm_kernel(const float* __restrict__ A,
                                                           const float* __restrict__ B,
                                                           const float* __restrict__ bias,
                                                           const float* __restrict__ Rd,
                                                           float* __restrict__ C, int M, int N,
                                                           int K) {
    extern __shared__ float sm[];
    int t = threadIdx.x;
    int warp = t >> 5, lane = t & 31;
    int gid = lane >> 2, tig = lane & 3;
    int m0 = blockIdx.y * 128, n0 = blockIdx.x * 256;
    int wm = (warp & 1) * 64, wn = (warp >> 1) * 32;

    float acc[4][4][4];
#pragma unroll
    for (int i = 0; i < 4; i++)
#pragma unroll
        for (int j = 0; j < 4; j++)
#pragma unroll
            for (int r = 0; r < 4; r++) acc[i][j][r] = 0.f;

    unsigned smBase = (unsigned)__cvta_generic_to_shared(sm);
    // A fill: thread -> row = t>>2 (0..127), kc = (t&3)*4
    int arow = t >> 2, acol = (t & 3) * 4;
    unsigned aDst = smBase + (unsigned)(arow * AST + acol) * 4u;
    const float* Ag = A + (size_t)(m0 + arow) * K + acol;
    // B fill: 2 chunks: c = i*512+t -> krow = c>>6, col = (c&63)*4
    int bk0 = t >> 6, bc0 = (t & 63) * 4;
    unsigned bDst0 = smBase + (unsigned)(ASZ + bk0 * BST + bc0) * 4u;
    const float* Bg0 = B + (size_t)bk0 * N + n0 + bc0;
    unsigned bDst1 = smBase + (unsigned)(ASZ + (bk0 + 8) * BST + bc0) * 4u;
    const float* Bg1 = B + (size_t)(bk0 + 8) * N + n0 + bc0;

    const int KT = K >> 4;

#define FILLG(J)                                                   \
    {                                                              \
        int _j = (J);                                              \
        unsigned so = (unsigned)((_j % 3) * SSZ) * 4u;             \
        int ko = _j << 4;                                          \
        cpa16(aDst + so, Ag + ko);                                 \
        cpa16(bDst0 + so, Bg0 + (size_t)ko * N);                   \
        cpa16(bDst1 + so, Bg1 + (size_t)ko * N);                   \
        asm volatile("cp.async.commit_group;");                    \
    }

    FILLG(0);
    FILLG(1);

    for (int kt = 0; kt < KT; kt++) {
        if (kt + 2 < KT) {
            FILLG(kt + 2);
            asm volatile("cp.async.wait_group 2;");
        } else if (kt + 1 < KT) {
            asm volatile("cp.async.wait_group 1;");
        } else {
            asm volatile("cp.async.wait_group 0;");
        }
        __syncthreads();
        const float* as = sm + (kt % 3) * SSZ;
        const float* bs = as + ASZ;
#pragma unroll
        for (int kk = 0; kk < 16; kk += 8) {
            unsigned af[4][4], bf[4][2];
#pragma unroll
            for (int mt = 0; mt < 4; mt++) {
                int rb = wm + mt * 16 + gid;
                af[mt][0] = f2tf32(as[rb * AST + kk + tig]);
                af[mt][1] = f2tf32(as[(rb + 8) * AST + kk + tig]);
                af[mt][2] = f2tf32(as[rb * AST + kk + tig + 4]);
                af[mt][3] = f2tf32(as[(rb + 8) * AST + kk + tig + 4]);
            }
#pragma unroll
            for (int nt = 0; nt < 4; nt++) {
                int cb = wn + nt * 8 + gid;
                bf[nt][0] = f2tf32(bs[(kk + tig) * BST + cb]);
                bf[nt][1] = f2tf32(bs[(kk + tig + 4) * BST + cb]);
            }
#pragma unroll
            for (int mt = 0; mt < 4; mt++)
#pragma unroll
                for (int nt = 0; nt < 4; nt++) {
                    asm volatile(
                        "mma.sync.aligned.m16n8k8.row.col.f32.tf32.tf32.f32 "
                        "{%0,%1,%2,%3}, {%4,%5,%6,%7}, {%8,%9}, {%0,%1,%2,%3};\n"
                        : "+f"(acc[mt][nt][0]), "+f"(acc[mt][nt][1]), "+f"(acc[mt][nt][2]),
                          "+f"(acc[mt][nt][3])
                        : "r"(af[mt][0]), "r"(af[mt][1]), "r"(af[mt][2]), "r"(af[mt][3]),
                          "r"(bf[nt][0]), "r"(bf[nt][1]));
                }
        }
        __syncthreads();
    }

    // epilogue
#pragma unroll
    for (int mt = 0; mt < 4; mt++) {
        int row = m0 + wm + mt * 16 + gid;
#pragma unroll
        for (int nt = 0; nt < 4; nt++) {
            int col = n0 + wn + nt * 8 + tig * 2;
            float b0 = bias[col], b1 = bias[col + 1];
            float v0 = acc[mt][nt][0] + b0;
            float v1 = acc[mt][nt][1] + b1;
            float v2 = acc[mt][nt][2] + b0;
            float v3 = acc[mt][nt][3] + b1;
            if (EPI == 1) {
                v0 = gelu_f(v0); v1 = gelu_f(v1); v2 = gelu_f(v2); v3 = gelu_f(v3);
            }
            size_t o0 = (size_t)row * N + col;
            size_t o2 = (size_t)(row + 8) * N + col;
            if (Rd != nullptr) {
                float2 r0 = *(const float2*)&Rd[o0];
                float2 r2 = *(const float2*)&Rd[o2];
                v0 += r0.x; v1 += r0.y; v2 += r2.x; v3 += r2.y;
            }
            *(float2*)&C[o0] = make_float2(v0, v1);
            *(float2*)&C[o2] = make_float2(v2, v3);
        }
    }
}

// ---------------- Hebbian chunked linear attention ----------------
__device__ __forceinline__ int ksw(int s, int d) {
    return s * 64 + (((((d >> 2) ^ (s & 15)) & 15) << 2) | (d & 3));
}
__device__ __forceinline__ int ksw4(int s, int d4) {
    return s * 64 + ((((d4 ^ (s & 15)) & 15) << 2));
}

__global__ __launch_bounds__(256) void heb_intra_kernel() {
    int bid = blockIdx.x;
    int c = bid & 31;
    int bh = bid >> 5;
    int h = bh & 7;
    int b = bh >> 3;
    int t0 = b * Nseq + c * 64;
    __shared__ float shQ[4096];
    __shared__ float shK[4096];
    __shared__ float shS[4096];
    int t = threadIdx.x;

    if (t < 64) shS[t] = g_gamma[t0 + t];
    __syncthreads();
    if (t == 0) {
        float cum = 0.f;
        for (int i = 0; i < 64; i++) {
            cum += shS[i];
            shS[i] = expf(-DT_C * cum);
        }
        g_Pl[bh * 32 + c] = shS[63];
    }
    __syncthreads();
    if (t < 64) shS[64 + t] = 1.f / shS[t];
    __syncthreads();

    for (int idx = t; idx < 4096; idx += 256) {
        int i = idx >> 6, d = idx & 63;
        size_t qb = (size_t)(t0 + i) * 1536 + h * 64 + d;
        float qs = g_qkv[qb] * shS[i];
        shQ[i * 64 + d] = qs;
        g_Qs[(size_t)(t0 + i) * 512 + h * 64 + d] = qs;
        shK[ksw(i, d)] = g_qkv[qb + 512] * shS[64 + i];
    }
    __syncthreads();

    {
        int i0 = (t >> 4) * 4, s0 = (t & 15) * 4;
        float accS[4][4];
#pragma unroll
        for (int r = 0; r < 4; r++)
#pragma unroll
            for (int q = 0; q < 4; q++) accS[r][q] = 0.f;
#pragma unroll
        for (int d4 = 0; d4 < 16; d4++) {
            float4 qa[4], ka[4];
#pragma unroll
            for (int r = 0; r < 4; r++) {
                qa[r] = *(const float4*)&shQ[(i0 + r) * 64 + d4 * 4];
                ka[r] = *(const float4*)&shK[ksw4(s0 + r, d4)];
            }
#pragma unroll
            for (int r = 0; r < 4; r++)
#pragma unroll
                for (int q = 0; q < 4; q++)
                    accS[r][q] += qa[r].x * ka[q].x + qa[r].y * ka[q].y + qa[r].z * ka[q].z +
                                  qa[r].w * ka[q].w;
        }
        __syncthreads();
#pragma unroll
        for (int r = 0; r < 4; r++)
#pragma unroll
            for (int q = 0; q < 4; q++) {
                int i = i0 + r, s = s0 + q;
                shS[i * 64 + s] = (s <= i) ? ETA_C * accS[r][q] : 0.f;
            }
    }
    __syncthreads();

    for (int idx = t; idx < 4096; idx += 256) {
        int i = idx >> 6, d = idx & 63;
        shQ[i * 64 + d] = g_qkv[(size_t)(t0 + i) * 1536 + 1024 + h * 64 + d];
    }
    __syncthreads();

    {
        int i0 = (t >> 4) * 4, e0 = (t & 15) * 4;
        float accO[4][4];
#pragma unroll
        for (int r = 0; r < 4; r++)
#pragma unroll
            for (int q = 0; q < 4; q++) accO[r][q] = 0.f;
        for (int s = 0; s < 64; s++) {
            float4 vv = *(const float4*)&shQ[s * 64 + e0];
            float sv[4];
#pragma unroll
            for (int r = 0; r < 4; r++) sv[r] = shS[(i0 + r) * 64 + s];
#pragma unroll
            for (int r = 0; r < 4; r++) {
                accO[r][0] += sv[r] * vv.x;
                accO[r][1] += sv[r] * vv.y;
                accO[r][2] += sv[r] * vv.z;
                accO[r][3] += sv[r] * vv.w;
            }
        }
#pragma unroll
        for (int r = 0; r < 4; r++) {
            float4 o4 = make_float4(accO[r][0], accO[r][1], accO[r][2], accO[r][3]);
            *(float4*)&g_Oin[(size_t)(t0 + i0 + r) * 512 + h * 64 + e0] = o4;
        }
    }

    {
        int d0 = (t >> 4) * 4, e0 = (t & 15) * 4;
        float accU[4][4];
#pragma unroll
        for (int r = 0; r < 4; r++)
#pragma unroll
            for (int q = 0; q < 4; q++) accU[r][q] = 0.f;
        for (int s = 0; s < 64; s++) {
            float4 vv = *(const float4*)&shQ[s * 64 + e0];
            float kv[4];
#pragma unroll
            for (int r = 0; r < 4; r++) kv[r] = shK[ksw(s, d0 + r)];
#pragma unroll
            for (int r = 0; r < 4; r++) {
                accU[r][0] += kv[r] * vv.x;
                accU[r][1] += kv[r] * vv.y;
                accU[r][2] += kv[r] * vv.z;
                accU[r][3] += kv[r] * vv.w;
            }
        }
        size_t ub = ((size_t)bh * 32 + c) * 4096;
#pragma unroll
        for (int r = 0; r < 4; r++) {
            float4 u4 = make_float4(accU[r][0], accU[r][1], accU[r][2], accU[r][3]);
            *(float4*)&g_U[ub + (d0 + r) * 64 + e0] = u4;
        }
    }
}

__global__ void heb_state_kernel() {
    int bh = blockIdx.x;
    int t = threadIdx.x;
    float4 W[4];
#pragma unroll
    for (int j = 0; j < 4; j++) W[j] = make_float4(0.f, 0.f, 0.f, 0.f);
    for (int c = 0; c < 32; c++) {
        size_t off = ((size_t)bh * 32 + c) * 4096 + t * 16;
        float pl = g_Pl[bh * 32 + c];
#pragma unroll
        for (int j = 0; j < 4; j++) {
            float4 u = *(const float4*)&g_U[off + j * 4];
            *(float4*)&g_Wst[off + j * 4] = W[j];
            W[j].x = pl * (W[j].x + ETA_C * u.x);
            W[j].y = pl * (W[j].y + ETA_C * u.y);
            W[j].z = pl * (W[j].z + ETA_C * u.z);
            W[j].w = pl * (W[j].w + ETA_C * u.w);
        }
    }
}

__global__ __launch_bounds__(256) void heb_inter_kernel() {
    int bid = blockIdx.x;
    int c = bid & 31;
    int bh = bid >> 5;
    int h = bh & 7;
    int b = bh >> 3;
    int t0 = b * Nseq + c * 64;
    __shared__ float shQ2[4096];
    __shared__ float shW[4096];
    int t = threadIdx.x;
    size_t wb = ((size_t)bh * 32 + c) * 4096;
    for (int idx = t; idx < 4096; idx += 256) {
        int i = idx >> 6, d = idx & 63;
        shQ2[i * 64 + d] = g_Qs[(size_t)(t0 + i) * 512 + h * 64 + d];
        shW[idx] = g_Wst[wb + idx];
    }
    __syncthreads();
    int i0 = (t >> 4) * 4, e0 = (t & 15) * 4;
    float acc[4][4];
#pragma unroll
    for (int r = 0; r < 4; r++) {
        float4 o4 = *(const float4*)&g_Oin[(size_t)(t0 + i0 + r) * 512 + h * 64 + e0];
        acc[r][0] = o4.x; acc[r][1] = o4.y; acc[r][2] = o4.z; acc[r][3] = o4.w;
    }
    for (int d = 0; d < 64; d++) {
        float4 wv = *(const float4*)&shW[d * 64 + e0];
        float qv[4];
#pragma unroll
        for (int r = 0; r < 4; r++) qv[r] = shQ2[(i0 + r) * 64 + d];
#pragma unroll
        for (int r = 0; r < 4; r++) {
            acc[r][0] += qv[r] * wv.x;
            acc[r][1] += qv[r] * wv.y;
            acc[r][2] += qv[r] * wv.z;
            acc[r][3] += qv[r] * wv.w;
        }
    }
#pragma unroll
    for (int r = 0; r < 4; r++) {
        float4 o4 = make_float4(acc[r][0], acc[r][1], acc[r][2], acc[r][3]);
        *(float4*)&g_heb[(size_t)(t0 + i0 + r) * 512 + h * 64 + e0] = o4;
    }
}

// ---------------- launch ----------------
extern "C" void kernel_launch(void* const* d_in, const int* in_sizes, int n_in,
                              void* d_out, int out_size) {
    const float* x     = (const float*)d_in[0];
    const float* ln1_g = (const float*)d_in[1];
    const float* ln1_b = (const float*)d_in[2];
    const float* ln2_g = (const float*)d_in[3];
    const float* ln2_b = (const float*)d_in[4];
    const float* ln3_g = (const float*)d_in[5];
    const float* ln3_b = (const float*)d_in[6];
    const float* w_pot = (const float*)d_in[7];
    const float* b_pot = (const float*)d_in[8];
    const float* w_bk  = (const float*)d_in[9];
    const float* b_bk  = (const float*)d_in[10];
    const float* w_qkv = (const float*)d_in[11];
    const float* b_qkv = (const float*)d_in[12];
    const float* w_out = (const float*)d_in[13];
    const float* b_out = (const float*)d_in[14];
    const float* w_ff1 = (const float*)d_in[15];
    const float* b_ff1 = (const float*)d_in[16];
    const float* w_ff2 = (const float*)d_in[17];
    const float* b_ff2 = (const float*)d_in[18];
    float* out = (float*)d_out;

    float *p_xn2, *p_qkv, *p_heb, *p_x1, *p_x2, *p_xn3, *p_ff;
    cudaGetSymbolAddress((void**)&p_xn2, g_xn2);
    cudaGetSymbolAddress((void**)&p_qkv, g_qkv);
    cudaGetSymbolAddress((void**)&p_heb, g_heb);
    cudaGetSymbolAddress((void**)&p_x1, g_x1);
    cudaGetSymbolAddress((void**)&p_x2, g_x2);
    cudaGetSymbolAddress((void**)&p_xn3, g_xn3);
    cudaGetSymbolAddress((void**)&p_ff, g_ff);

    cudaFuncSetAttribute(tf32_gemm_kernel<0>, cudaFuncAttributeMaxDynamicSharedMemorySize, GSMEM);
    cudaFuncSetAttribute(tf32_gemm_kernel<1>, cudaFuncAttributeMaxDynamicSharedMemorySize, GSMEM);

    ln1_pot_kernel<<<Ttok, 256>>>(x, ln1_g, ln1_b, w_pot, b_pot);
    bk_scan_kernel<<<8, 128>>>();
    bk_res_ln2_kernel<<<Ttok, 256>>>(x, w_bk, b_bk, ln2_g, ln2_b);
    tf32_gemm_kernel<0><<<dim3(6, 64), 512, GSMEM>>>(p_xn2, w_qkv, b_qkv, nullptr, p_qkv, Ttok, 1536, 1024);
    heb_intra_kernel<<<1024, 256>>>();
    heb_state_kernel<<<32, 256>>>();
    heb_inter_kernel<<<1024, 256>>>();
    tf32_gemm_kernel<0><<<dim3(4, 64), 512, GSMEM>>>(p_heb, w_out, b_out, p_x1, p_x2, Ttok, 1024, 512);
    ln3_kernel<<<Ttok, 256>>>(ln3_g, ln3_b);
    tf32_gemm_kernel<1><<<dim3(16, 64), 512, GSMEM>>>(p_xn3, w_ff1, b_ff1, nullptr, p_ff, Ttok, 4096, 1024);
    tf32_gemm_kernel<0><<<dim3(4, 64), 512, GSMEM>>>(p_ff, w_ff2, b_ff2, p_x2, out, Ttok, 1024, 4096);
}

// round 10
// speedup vs baseline: 1.6212x; 1.6212x over previous
#include <cuda_runtime.h>
#include <cuda_fp16.h>
#include <stdint.h>
#include <math.h>

#define Bdim 4
#define Nseq 2048
#define Ddim 1024
#define FFd  4096
#define Ttok 8192
#define ETA_C 0.1f
#define DT_C  0.01f

// ---------------- scratch ----------------
__device__ float g_V[Ttok];
__device__ float g_gamma[Ttok];
__device__ float g_a[Ttok * 2];
__device__ float g_bcf[Ttok * 2];
__device__ float g_x1[(size_t)Ttok * Ddim];
__device__ float g_qkv[(size_t)Ttok * 1536];
__device__ float g_Qs[(size_t)Ttok * 512];
__device__ float g_Oin[(size_t)Ttok * 512];
__device__ float g_U[32 * 32 * 4096];
__device__ float g_Wst[32 * 32 * 4096];
__device__ float g_Pl[32 * 32];
__device__ float g_x2[(size_t)Ttok * Ddim];
// fp16 activations
__device__ __half g_xn2h[(size_t)Ttok * Ddim];
__device__ __half g_xn3h[(size_t)Ttok * Ddim];
__device__ __half g_hebh[(size_t)Ttok * 512];
__device__ __half g_ffh[(size_t)Ttok * FFd];
// fp16 transposed weights [N][K]
__device__ __half g_wqt[(size_t)1536 * Ddim];
__device__ __half g_wot[(size_t)Ddim * 512];
__device__ __half g_w1t[(size_t)FFd * Ddim];
__device__ __half g_w2t[(size_t)Ddim * FFd];

// ---------------- helpers ----------------
__device__ __forceinline__ float blk_sum256(float v, float* sh) {
    int t = threadIdx.x;
#pragma unroll
    for (int o = 16; o > 0; o >>= 1) v += __shfl_down_sync(0xffffffffu, v, o);
    if ((t & 31) == 0) sh[t >> 5] = v;
    __syncthreads();
    if (t < 32) {
        float r = (t < 8) ? sh[t] : 0.f;
#pragma unroll
        for (int o = 4; o > 0; o >>= 1) r += __shfl_down_sync(0xffffffffu, r, o);
        if (t == 0) sh[0] = r;
    }
    __syncthreads();
    float r = sh[0];
    __syncthreads();
    return r;
}

__device__ __forceinline__ float gelu_f(float x) {
    float x3 = x * x * x;
    float u = 0.7978845608028654f * (x + 0.044715f * x3);
    return 0.5f * x * (1.f + tanhf(u));
}

// ---------------- weight transpose to fp16 [N][K] ----------------
__global__ void conv_wh_kernel(const float* __restrict__ W, __half* __restrict__ out, int K,
                               int N) {
    __shared__ float tile[32][33];
    int t = threadIdx.x;
    int tx = t & 31, ty = t >> 5;  // 32 x 8
    int n0 = blockIdx.x * 32, k0 = blockIdx.y * 32;
#pragma unroll
    for (int r = 0; r < 4; r++)
        tile[ty + r * 8][tx] = W[(size_t)(k0 + ty + r * 8) * N + n0 + tx];
    __syncthreads();
#pragma unroll
    for (int r = 0; r < 4; r++)
        out[(size_t)(n0 + ty + r * 8) * K + k0 + tx] = __float2half(tile[tx][ty + r * 8]);
}

// ---------------- K1: LN1 + potential ----------------
__global__ void ln1_pot_kernel(const float* __restrict__ x, const float* __restrict__ g1,
                               const float* __restrict__ b1, const float* __restrict__ wpot,
                               const float* __restrict__ bpot) {
    int row = blockIdx.x;
    int t = threadIdx.x;
    __shared__ float sh[8];
    const float4* xr = (const float4*)(x + (size_t)row * Ddim);
    float4 xv = xr[t];
    float s = xv.x + xv.y + xv.z + xv.w;
    float ss = xv.x * xv.x + xv.y * xv.y + xv.z * xv.z + xv.w * xv.w;
    s = blk_sum256(s, sh);
    ss = blk_sum256(ss, sh);
    float m = s * (1.f / Ddim);
    float var = ss * (1.f / Ddim) - m * m;
    float rstd = rsqrtf(var + 1e-5f);
    float xa[4] = {xv.x, xv.y, xv.z, xv.w};
    float p0 = 0.f, p1 = 0.f;
#pragma unroll
    for (int j = 0; j < 4; j++) {
        int col = t * 4 + j;
        float xn = (xa[j] - m) * rstd * g1[col] + b1[col];
        p0 += xn * wpot[col * 2];
        p1 += xn * wpot[col * 2 + 1];
    }
    p0 = blk_sum256(p0, sh);
    p1 = blk_sum256(p1, sh);
    if (t == 0) {
        g_V[row] = p0 + bpot[0];
        float z = p1 + bpot[1];
        float sp = (z > 20.f) ? z : log1pf(expf(z));
        g_gamma[row] = sp + 0.1f;
    }
}

// ---------------- K2: continued fractions ----------------
__global__ void bk_scan_kernel() {
    int bb = blockIdx.x >> 1;
    int dir = blockIdx.x & 1;
    __shared__ float dre[128], dii[128], ore[128], oim[128];
    int t = threadIdx.x;
    float pre = 0.f, pim = 0.f;
    float* out = dir ? g_bcf : g_a;
    for (int c = 0; c < 16; c++) {
        int j = c * 128 + t;
        int pos = dir ? (Nseq - 1 - j) : j;
        int gi = bb * Nseq + pos;
        dre[t] = g_V[gi] + 2.f;
        dii[t] = -g_gamma[gi];
        __syncthreads();
        if (t == 0) {
            for (int u = 0; u < 128; u++) {
                float ar, ai;
                if (c == 0 && u == 0) {
                    ar = dre[0]; ai = dii[0];
                } else {
                    float inv = 1.f / (pre * pre + pim * pim);
                    ar = dre[u] - pre * inv;
                    ai = dii[u] + pim * inv;
                }
                ore[u] = ar; oim[u] = ai;
                pre = ar; pim = ai;
            }
        }
        __syncthreads();
        out[gi * 2] = ore[t];
        out[gi * 2 + 1] = oim[t];
        __syncthreads();
    }
}

// ---------------- K3: BK + residual + LN2 -> fp16 ----------------
__global__ void bk_res_ln2_kernel(const float* __restrict__ x, const float* __restrict__ wbk,
                                  const float* __restrict__ bbk, const float* __restrict__ g2,
                                  const float* __restrict__ b2) {
    int row = blockIdx.x;
    int t = threadIdx.x;
    __shared__ float sh[8];
    __shared__ float f01[2];
    if (t == 0) {
        float are = g_a[row * 2], aim = g_a[row * 2 + 1];
        float bre = g_bcf[row * 2], bim = g_bcf[row * 2 + 1];
        float dr = g_V[row] + 2.f, di = -g_gamma[row];
        float nr = are + bre - dr, ni = aim + bim - di;
        float inv = 1.f / (nr * nr + ni * ni);
        f01[0] = nr * inv;
        f01[1] = -ni * inv;
    }
    __syncthreads();
    float f0 = f01[0], f1 = f01[1];
    size_t base = (size_t)row * Ddim;
    float y[4];
    float s = 0.f, ss = 0.f;
#pragma unroll
    for (int j = 0; j < 4; j++) {
        int col = t * 4 + j;
        float v = x[base + col] + f0 * wbk[col] + f1 * wbk[Ddim + col] + bbk[col];
        y[j] = v;
        s += v;
        ss += v * v;
        g_x1[base + col] = v;
    }
    s = blk_sum256(s, sh);
    ss = blk_sum256(ss, sh);
    float m = s * (1.f / Ddim);
    float var = ss * (1.f / Ddim) - m * m;
    float rstd = rsqrtf(var + 1e-5f);
    __half2 h2[2];
#pragma unroll
    for (int j = 0; j < 2; j++) {
        float v0 = (y[2 * j] - m) * rstd * g2[t * 4 + 2 * j] + b2[t * 4 + 2 * j];
        float v1 = (y[2 * j + 1] - m) * rstd * g2[t * 4 + 2 * j + 1] + b2[t * 4 + 2 * j + 1];
        h2[j] = __floats2half2_rn(v0, v1);
    }
    *(uint2*)&g_xn2h[base + t * 4] = make_uint2(*(unsigned*)&h2[0], *(unsigned*)&h2[1]);
}

// ---------------- LN3 -> fp16 ----------------
__global__ void ln3_kernel(const float* __restrict__ g3, const float* __restrict__ b3) {
    int row = blockIdx.x;
    int t = threadIdx.x;
    __shared__ float sh[8];
    size_t base = (size_t)row * Ddim;
    float4 xv = *(const float4*)&g_x2[base + t * 4];
    float s = xv.x + xv.y + xv.z + xv.w;
    float ss = xv.x * xv.x + xv.y * xv.y + xv.z * xv.z + xv.w * xv.w;
    s = blk_sum256(s, sh);
    ss = blk_sum256(ss, sh);
    float m = s * (1.f / Ddim);
    float var = ss * (1.f / Ddim) - m * m;
    float rstd = rsqrtf(var + 1e-5f);
    float xa[4] = {xv.x, xv.y, xv.z, xv.w};
    __half2 h2[2];
#pragma unroll
    for (int j = 0; j < 2; j++) {
        float v0 = (xa[2 * j] - m) * rstd * g3[t * 4 + 2 * j] + b3[t * 4 + 2 * j];
        float v1 = (xa[2 * j + 1] - m) * rstd * g3[t * 4 + 2 * j + 1] + b3[t * 4 + 2 * j + 1];
        h2[j] = __floats2half2_rn(v0, v1);
    }
    *(uint2*)&g_xn3h[base + t * 4] = make_uint2(*(unsigned*)&h2[0], *(unsigned*)&h2[1]);
}

// ---------------- FP16 tensor GEMM: 128x128, 8 warps (2x4 of 64x32), K-step 32 ----------------
// A[M][K] fp16 row-major; Bt[N][K] fp16 row-major; C = A @ Bt^T + bias (+Rd / gelu->fp16)
#define HST 40  // smem row stride in halves (32 + 8 pad)

__device__ __forceinline__ void cpa16(unsigned dst, const void* src) {
    asm volatile("cp.async.ca.shared.global [%0], [%1], 16;\n" ::"r"(dst), "l"(src));
}

template <int EPI>  // 0: fp32 out (+Rd), 1: gelu -> fp16 out
__global__ __launch_bounds__(256, 2) void h16_gemm(const __half* __restrict__ A,
                                                   const __half* __restrict__ Bt,
                                                   const float* __restrict__ bias,
                                                   const float* __restrict__ Rd,
                                                   void* __restrict__ Cv, int M, int N, int K) {
    __shared__ __half As[2][128 * HST];
    __shared__ __half Bs[2][128 * HST];
    int t = threadIdx.x;
    int warp = t >> 5, lane = t & 31;
    int gid = lane >> 2, tig = lane & 3;
    int m0 = blockIdx.y * 128, n0 = blockIdx.x * 128;
    int wm = (warp >> 2) * 64, wn = (warp & 3) * 32;

    float acc[4][4][4];
#pragma unroll
    for (int i = 0; i < 4; i++)
#pragma unroll
        for (int j = 0; j < 4; j++)
#pragma unroll
            for (int r = 0; r < 4; r++) acc[i][j][r] = 0.f;

    unsigned aBase = (unsigned)__cvta_generic_to_shared(&As[0][0]);
    unsigned bBase = (unsigned)__cvta_generic_to_shared(&Bs[0][0]);
    // fill mapping: chunk c in [0,512): row = c>>2, kc8 = (c&3)*8
    int r0 = t >> 2, kc0 = (t & 3) * 8;
    int r1 = (t + 256) >> 2, kc1 = ((t + 256) & 3) * 8;  // = r0+64, same kc
    unsigned aD0 = aBase + (unsigned)(r0 * HST + kc0) * 2u;
    unsigned aD1 = aBase + (unsigned)(r1 * HST + kc1) * 2u;
    unsigned bD0 = bBase + (unsigned)(r0 * HST + kc0) * 2u;
    unsigned bD1 = bBase + (unsigned)(r1 * HST + kc1) * 2u;
    const __half* Ag0 = A + (size_t)(m0 + r0) * K + kc0;
    const __half* Ag1 = A + (size_t)(m0 + r1) * K + kc1;
    const __half* Bg0 = Bt + (size_t)(n0 + r0) * K + kc0;
    const __half* Bg1 = Bt + (size_t)(n0 + r1) * K + kc1;
    const unsigned SOFF = (unsigned)(128 * HST) * 2u;

    const int KT = K >> 5;

#define HFILL(J)                                   \
    {                                              \
        int _j = (J);                              \
        unsigned so = (_j & 1) ? SOFF : 0u;        \
        int ko = _j << 5;                          \
        cpa16(aD0 + so, Ag0 + ko);                 \
        cpa16(aD1 + so, Ag1 + ko);                 \
        cpa16(bD0 + so, Bg0 + ko);                 \
        cpa16(bD1 + so, Bg1 + ko);                 \
        asm volatile("cp.async.commit_group;");    \
    }

    HFILL(0);

    for (int kt = 0; kt < KT; kt++) {
        if (kt + 1 < KT) {
            HFILL(kt + 1);
            asm volatile("cp.async.wait_group 1;");
        } else {
            asm volatile("cp.async.wait_group 0;");
        }
        __syncthreads();
        const __half* as = &As[kt & 1][0];
        const __half* bs = &Bs[kt & 1][0];
#pragma unroll
        for (int kk = 0; kk < 32; kk += 16) {
            unsigned af[4][4], bf[4][2];
#pragma unroll
            for (int mt = 0; mt < 4; mt++) {
                int rb = wm + mt * 16 + gid;
                af[mt][0] = *(const unsigned*)(as + rb * HST + kk + tig * 2);
                af[mt][1] = *(const unsigned*)(as + (rb + 8) * HST + kk + tig * 2);
                af[mt][2] = *(const unsigned*)(as + rb * HST + kk + tig * 2 + 8);
                af[mt][3] = *(const unsigned*)(as + (rb + 8) * HST + kk + tig * 2 + 8);
            }
#pragma unroll
            for (int nt = 0; nt < 4; nt++) {
                int cb = wn + nt * 8 + gid;
                bf[nt][0] = *(const unsigned*)(bs + cb * HST + kk + tig * 2);
                bf[nt][1] = *(const unsigned*)(bs + cb * HST + kk + tig * 2 + 8);
            }
#pragma unroll
            for (int mt = 0; mt < 4; mt++)
#pragma unroll
                for (int nt = 0; nt < 4; nt++) {
                    asm volatile(
                        "mma.sync.aligned.m16n8k16.row.col.f32.f16.f16.f32 "
                        "{%0,%1,%2,%3}, {%4,%5,%6,%7}, {%8,%9}, {%0,%1,%2,%3};\n"
                        : "+f"(acc[mt][nt][0]), "+f"(acc[mt][nt][1]), "+f"(acc[mt][nt][2]),
                          "+f"(acc[mt][nt][3])
                        : "r"(af[mt][0]), "r"(af[mt][1]), "r"(af[mt][2]), "r"(af[mt][3]),
                          "r"(bf[nt][0]), "r"(bf[nt][1]));
                }
        }
        __syncthreads();
    }

    // epilogue
#pragma unroll
    for (int mt = 0; mt < 4; mt++) {
        int row = m0 + wm + mt * 16 + gid;
#pragma unroll
        for (int nt = 0; nt < 4; nt++) {
            int col = n0 + wn + nt * 8 + tig * 2;
            float b0 = bias[col], b1 = bias[col + 1];
            float v0 = acc[mt][nt][0] + b0;
            float v1 = acc[mt][nt][1] + b1;
            float v2 = acc[mt][nt][2] + b0;
            float v3 = acc[mt][nt][3] + b1;
            if (EPI == 1) {
                v0 = gelu_f(v0); v1 = gelu_f(v1); v2 = gelu_f(v2); v3 = gelu_f(v3);
                __half* C = (__half*)Cv;
                __half2 p = __floats2half2_rn(v0, v1);
                __half2 q = __floats2half2_rn(v2, v3);
                *(unsigned*)&C[(size_t)row * N + col] = *(unsigned*)&p;
                *(unsigned*)&C[(size_t)(row + 8) * N + col] = *(unsigned*)&q;
            } else {
                float* C = (float*)Cv;
                size_t o0 = (size_t)row * N + col;
                size_t o2 = (size_t)(row + 8) * N + col;
                if (Rd != nullptr) {
                    float2 rr0 = *(const float2*)&Rd[o0];
                    float2 rr2 = *(const float2*)&Rd[o2];
                    v0 += rr0.x; v1 += rr0.y; v2 += rr2.x; v3 += rr2.y;
                }
                *(float2*)&C[o0] = make_float2(v0, v1);
                *(float2*)&C[o2] = make_float2(v2, v3);
            }
        }
    }
}

// ---------------- Hebbian chunked linear attention ----------------
__device__ __forceinline__ int ksw(int s, int d) {
    return s * 64 + (((((d >> 2) ^ (s & 15)) & 15) << 2) | (d & 3));
}
__device__ __forceinline__ int ksw4(int s, int d4) {
    return s * 64 + ((((d4 ^ (s & 15)) & 15) << 2));
}

__global__ __launch_bounds__(256) void heb_intra_kernel() {
    int bid = blockIdx.x;
    int c = bid & 31;
    int bh = bid >> 5;
    int h = bh & 7;
    int b = bh >> 3;
    int t0 = b * Nseq + c * 64;
    __shared__ float shQ[4096];
    __shared__ float shK[4096];
    __shared__ float shS[4096];
    int t = threadIdx.x;

    if (t < 64) shS[t] = g_gamma[t0 + t];
    __syncthreads();
    if (t == 0) {
        float cum = 0.f;
        for (int i = 0; i < 64; i++) {
            cum += shS[i];
            shS[i] = expf(-DT_C * cum);
        }
        g_Pl[bh * 32 + c] = shS[63];
    }
    __syncthreads();
    if (t < 64) shS[64 + t] = 1.f / shS[t];
    __syncthreads();

    for (int idx = t; idx < 4096; idx += 256) {
        int i = idx >> 6, d = idx & 63;
        size_t qb = (size_t)(t0 + i) * 1536 + h * 64 + d;
        float qs = g_qkv[qb] * shS[i];
        shQ[i * 64 + d] = qs;
        g_Qs[(size_t)(t0 + i) * 512 + h * 64 + d] = qs;
        shK[ksw(i, d)] = g_qkv[qb + 512] * shS[64 + i];
    }
    __syncthreads();

    {
        int i0 = (t >> 4) * 4, s0 = (t & 15) * 4;
        float accS[4][4];
#pragma unroll
        for (int r = 0; r < 4; r++)
#pragma unroll
            for (int q = 0; q < 4; q++) accS[r][q] = 0.f;
#pragma unroll
        for (int d4 = 0; d4 < 16; d4++) {
            float4 qa[4], ka[4];
#pragma unroll
            for (int r = 0; r < 4; r++) {
                qa[r] = *(const float4*)&shQ[(i0 + r) * 64 + d4 * 4];
                ka[r] = *(const float4*)&shK[ksw4(s0 + r, d4)];
            }
#pragma unroll
            for (int r = 0; r < 4; r++)
#pragma unroll
                for (int q = 0; q < 4; q++)
                    accS[r][q] += qa[r].x * ka[q].x + qa[r].y * ka[q].y + qa[r].z * ka[q].z +
                                  qa[r].w * ka[q].w;
        }
        __syncthreads();
#pragma unroll
        for (int r = 0; r < 4; r++)
#pragma unroll
            for (int q = 0; q < 4; q++) {
                int i = i0 + r, s = s0 + q;
                shS[i * 64 + s] = (s <= i) ? ETA_C * accS[r][q] : 0.f;
            }
    }
    __syncthreads();

    for (int idx = t; idx < 4096; idx += 256) {
        int i = idx >> 6, d = idx & 63;
        shQ[i * 64 + d] = g_qkv[(size_t)(t0 + i) * 1536 + 1024 + h * 64 + d];
    }
    __syncthreads();

    {
        int i0 = (t >> 4) * 4, e0 = (t & 15) * 4;
        float accO[4][4];
#pragma unroll
        for (int r = 0; r < 4; r++)
#pragma unroll
            for (int q = 0; q < 4; q++) accO[r][q] = 0.f;
        for (int s = 0; s < 64; s++) {
            float4 vv = *(const float4*)&shQ[s * 64 + e0];
            float sv[4];
#pragma unroll
            for (int r = 0; r < 4; r++) sv[r] = shS[(i0 + r) * 64 + s];
#pragma unroll
            for (int r = 0; r < 4; r++) {
                accO[r][0] += sv[r] * vv.x;
                accO[r][1] += sv[r] * vv.y;
                accO[r][2] += sv[r] * vv.z;
                accO[r][3] += sv[r] * vv.w;
            }
        }
#pragma unroll
        for (int r = 0; r < 4; r++) {
            float4 o4 = make_float4(accO[r][0], accO[r][1], accO[r][2], accO[r][3]);
            *(float4*)&g_Oin[(size_t)(t0 + i0 + r) * 512 + h * 64 + e0] = o4;
        }
    }

    {
        int d0 = (t >> 4) * 4, e0 = (t & 15) * 4;
        float accU[4][4];
#pragma unroll
        for (int r = 0; r < 4; r++)
#pragma unroll
            for (int q = 0; q < 4; q++) accU[r][q] = 0.f;
        for (int s = 0; s < 64; s++) {
            float4 vv = *(const float4*)&shQ[s * 64 + e0];
            float kv[4];
#pragma unroll
            for (int r = 0; r < 4; r++) kv[r] = shK[ksw(s, d0 + r)];
#pragma unroll
            for (int r = 0; r < 4; r++) {
                accU[r][0] += kv[r] * vv.x;
                accU[r][1] += kv[r] * vv.y;
                accU[r][2] += kv[r] * vv.z;
                accU[r][3] += kv[r] * vv.w;
            }
        }
        size_t ub = ((size_t)bh * 32 + c) * 4096;
#pragma unroll
        for (int r = 0; r < 4; r++) {
            float4 u4 = make_float4(accU[r][0], accU[r][1], accU[r][2], accU[r][3]);
            *(float4*)&g_U[ub + (d0 + r) * 64 + e0] = u4;
        }
    }
}

__global__ void heb_state_kernel() {
    int bh = blockIdx.x;
    int t = threadIdx.x;
    float4 W[4];
#pragma unroll
    for (int j = 0; j < 4; j++) W[j] = make_float4(0.f, 0.f, 0.f, 0.f);
    for (int c = 0; c < 32; c++) {
        size_t off = ((size_t)bh * 32 + c) * 4096 + t * 16;
        float pl = g_Pl[bh * 32 + c];
#pragma unroll
        for (int j = 0; j < 4; j++) {
            float4 u = *(const float4*)&g_U[off + j * 4];
            *(float4*)&g_Wst[off + j * 4] = W[j];
            W[j].x = pl * (W[j].x + ETA_C * u.x);
            W[j].y = pl * (W[j].y + ETA_C * u.y);
            W[j].z = pl * (W[j].z + ETA_C * u.z);
            W[j].w = pl * (W[j].w + ETA_C * u.w);
        }
    }
}

__global__ __launch_bounds__(256) void heb_inter_kernel() {
    int bid = blockIdx.x;
    int c = bid & 31;
    int bh = bid >> 5;
    int h = bh & 7;
    int b = bh >> 3;
    int t0 = b * Nseq + c * 64;
    __shared__ float shQ2[4096];
    __shared__ float shW[4096];
    int t = threadIdx.x;
    size_t wb = ((size_t)bh * 32 + c) * 4096;
    for (int idx = t; idx < 4096; idx += 256) {
        int i = idx >> 6, d = idx & 63;
        shQ2[i * 64 + d] = g_Qs[(size_t)(t0 + i) * 512 + h * 64 + d];
        shW[idx] = g_Wst[wb + idx];
    }
    __syncthreads();
    int i0 = (t >> 4) * 4, e0 = (t & 15) * 4;
    float acc[4][4];
#pragma unroll
    for (int r = 0; r < 4; r++) {
        float4 o4 = *(const float4*)&g_Oin[(size_t)(t0 + i0 + r) * 512 + h * 64 + e0];
        acc[r][0] = o4.x; acc[r][1] = o4.y; acc[r][2] = o4.z; acc[r][3] = o4.w;
    }
    for (int d = 0; d < 64; d++) {
        float4 wv = *(const float4*)&shW[d * 64 + e0];
        float qv[4];
#pragma unroll
        for (int r = 0; r < 4; r++) qv[r] = shQ2[(i0 + r) * 64 + d];
#pragma unroll
        for (int r = 0; r < 4; r++) {
            acc[r][0] += qv[r] * wv.x;
            acc[r][1] += qv[r] * wv.y;
            acc[r][2] += qv[r] * wv.z;
            acc[r][3] += qv[r] * wv.w;
        }
    }
    __half2 p = __floats2half2_rn(acc[0][0], acc[0][1]);
#pragma unroll
    for (int r = 0; r < 4; r++) {
        __half2 h0 = __floats2half2_rn(acc[r][0], acc[r][1]);
        __half2 h1 = __floats2half2_rn(acc[r][2], acc[r][3]);
        *(uint2*)&g_hebh[(size_t)(t0 + i0 + r) * 512 + h * 64 + e0] =
            make_uint2(*(unsigned*)&h0, *(unsigned*)&h1);
    }
    (void)p;
}

// ---------------- launch ----------------
extern "C" void kernel_launch(void* const* d_in, const int* in_sizes, int n_in,
                              void* d_out, int out_size) {
    const float* x     = (const float*)d_in[0];
    const float* ln1_g = (const float*)d_in[1];
    const float* ln1_b = (const float*)d_in[2];
    const float* ln2_g = (const float*)d_in[3];
    const float* ln2_b = (const float*)d_in[4];
    const float* ln3_g = (const float*)d_in[5];
    const float* ln3_b = (const float*)d_in[6];
    const float* w_pot = (const float*)d_in[7];
    const float* b_pot = (const float*)d_in[8];
    const float* w_bk  = (const float*)d_in[9];
    const float* b_bk  = (const float*)d_in[10];
    const float* w_qkv = (const float*)d_in[11];
    const float* b_qkv = (const float*)d_in[12];
    const float* w_out = (const float*)d_in[13];
    const float* b_out = (const float*)d_in[14];
    const float* w_ff1 = (const float*)d_in[15];
    const float* b_ff1 = (const float*)d_in[16];
    const float* w_ff2 = (const float*)d_in[17];
    const float* b_ff2 = (const float*)d_in[18];
    float* out = (float*)d_out;

    float *p_qkv, *p_x1, *p_x2;
    __half *p_xn2h, *p_xn3h, *p_hebh, *p_ffh, *p_wqt, *p_wot, *p_w1t, *p_w2t;
    cudaGetSymbolAddress((void**)&p_qkv, g_qkv);
    cudaGetSymbolAddress((void**)&p_x1, g_x1);
    cudaGetSymbolAddress((void**)&p_x2, g_x2);
    cudaGetSymbolAddress((void**)&p_xn2h, g_xn2h);
    cudaGetSymbolAddress((void**)&p_xn3h, g_xn3h);
    cudaGetSymbolAddress((void**)&p_hebh, g_hebh);
    cudaGetSymbolAddress((void**)&p_ffh, g_ffh);
    cudaGetSymbolAddress((void**)&p_wqt, g_wqt);
    cudaGetSymbolAddress((void**)&p_wot, g_wot);
    cudaGetSymbolAddress((void**)&p_w1t, g_w1t);
    cudaGetSymbolAddress((void**)&p_w2t, g_w2t);

    // weight transpose+halve (independent)
    conv_wh_kernel<<<dim3(1536 / 32, 1024 / 32), 256>>>(w_qkv, p_wqt, 1024, 1536);
    conv_wh_kernel<<<dim3(1024 / 32, 512 / 32), 256>>>(w_out, p_wot, 512, 1024);
    conv_wh_kernel<<<dim3(4096 / 32, 1024 / 32), 256>>>(w_ff1, p_w1t, 1024, 4096);
    conv_wh_kernel<<<dim3(1024 / 32, 4096 / 32), 256>>>(w_ff2, p_w2t, 4096, 1024);

    ln1_pot_kernel<<<Ttok, 256>>>(x, ln1_g, ln1_b, w_pot, b_pot);
    bk_scan_kernel<<<8, 128>>>();
    bk_res_ln2_kernel<<<Ttok, 256>>>(x, w_bk, b_bk, ln2_g, ln2_b);
    h16_gemm<0><<<dim3(12, 64), 256>>>(p_xn2h, p_wqt, b_qkv, nullptr, p_qkv, Ttok, 1536, 1024);
    heb_intra_kernel<<<1024, 256>>>();
    heb_state_kernel<<<32, 256>>>();
    heb_inter_kernel<<<1024, 256>>>();
    h16_gemm<0><<<dim3(8, 64), 256>>>(p_hebh, p_wot, b_out, p_x1, p_x2, Ttok, 1024, 512);
    ln3_kernel<<<Ttok, 256>>>(ln3_g, ln3_b);
    h16_gemm<1><<<dim3(32, 64), 256>>>(p_xn3h, p_w1t, b_ff1, nullptr, p_ffh, Ttok, 4096, 1024);
    h16_gemm<0><<<dim3(8, 64), 256>>>(p_ffh, p_w2t, b_ff2, p_x2, out, Ttok, 1024, 4096);
}

// round 12
// speedup vs baseline: 1.7769x; 1.0961x over previous
#include <cuda_runtime.h>
#include <cuda_fp16.h>
#include <stdint.h>
#include <math.h>

#define Bdim 4
#define Nseq 2048
#define Ddim 1024
#define FFd  4096
#define Ttok 8192
#define ETA_C 0.1f
#define DT_C  0.01f

// ---------------- scratch ----------------
__device__ float g_V[Ttok];
__device__ float g_gamma[Ttok];
__device__ float g_a[Ttok * 2];
__device__ float g_bcf[Ttok * 2];
__device__ float g_P[Ttok];
__device__ float g_Pinv[Ttok];
__device__ float g_Plast[Bdim * 32];
__device__ float g_x1[(size_t)Ttok * Ddim];
__device__ float g_U[32 * 32 * 4096];
__device__ float g_Wst[32 * 32 * 4096];
__device__ float g_x2[(size_t)Ttok * Ddim];
// fp16 activations
__device__ __half g_qkvh[(size_t)Ttok * 1536];   // [q*P | k/P | v]
__device__ __half g_Oinh[(size_t)Ttok * 512];
__device__ __half g_xn2h[(size_t)Ttok * Ddim];
__device__ __half g_xn3h[(size_t)Ttok * Ddim];
__device__ __half g_hebh[(size_t)Ttok * 512];
__device__ __half g_ffh[(size_t)Ttok * FFd];
// fp16 transposed weights [N][K]
__device__ __half g_wqt[(size_t)1536 * Ddim];
__device__ __half g_wot[(size_t)Ddim * 512];
__device__ __half g_w1t[(size_t)FFd * Ddim];
__device__ __half g_w2t[(size_t)Ddim * FFd];

// ---------------- helpers ----------------
__device__ __forceinline__ float blk_sum256(float v, float* sh) {
    int t = threadIdx.x;
#pragma unroll
    for (int o = 16; o > 0; o >>= 1) v += __shfl_down_sync(0xffffffffu, v, o);
    if ((t & 31) == 0) sh[t >> 5] = v;
    __syncthreads();
    if (t < 32) {
        float r = (t < 8) ? sh[t] : 0.f;
#pragma unroll
        for (int o = 4; o > 0; o >>= 1) r += __shfl_down_sync(0xffffffffu, r, o);
        if (t == 0) sh[0] = r;
    }
    __syncthreads();
    float r = sh[0];
    __syncthreads();
    return r;
}

__device__ __forceinline__ float gelu_f(float x) {
    float x3 = x * x * x;
    float u = 0.7978845608028654f * (x + 0.044715f * x3);
    return 0.5f * x * (1.f + tanhf(u));
}

// ---------------- weight transpose to fp16 [N][K] ----------------
__global__ void conv_wh_kernel(const float* __restrict__ W, __half* __restrict__ out, int K,
                               int N) {
    __shared__ float tile[32][33];
    int t = threadIdx.x;
    int tx = t & 31, ty = t >> 5;
    int n0 = blockIdx.x * 32, k0 = blockIdx.y * 32;
#pragma unroll
    for (int r = 0; r < 4; r++)
        tile[ty + r * 8][tx] = W[(size_t)(k0 + ty + r * 8) * N + n0 + tx];
    __syncthreads();
#pragma unroll
    for (int r = 0; r < 4; r++)
        out[(size_t)(n0 + ty + r * 8) * K + k0 + tx] = __float2half(tile[tx][ty + r * 8]);
}

// ---------------- K1: LN1 + potential ----------------
__global__ void ln1_pot_kernel(const float* __restrict__ x, const float* __restrict__ g1,
                               const float* __restrict__ b1, const float* __restrict__ wpot,
                               const float* __restrict__ bpot) {
    int row = blockIdx.x;
    int t = threadIdx.x;
    __shared__ float sh[8];
    const float4* xr = (const float4*)(x + (size_t)row * Ddim);
    float4 xv = xr[t];
    float s = xv.x + xv.y + xv.z + xv.w;
    float ss = xv.x * xv.x + xv.y * xv.y + xv.z * xv.z + xv.w * xv.w;
    s = blk_sum256(s, sh);
    ss = blk_sum256(ss, sh);
    float m = s * (1.f / Ddim);
    float var = ss * (1.f / Ddim) - m * m;
    float rstd = rsqrtf(var + 1e-5f);
    float xa[4] = {xv.x, xv.y, xv.z, xv.w};
    float p0 = 0.f, p1 = 0.f;
#pragma unroll
    for (int j = 0; j < 4; j++) {
        int col = t * 4 + j;
        float xn = (xa[j] - m) * rstd * g1[col] + b1[col];
        p0 += xn * wpot[col * 2];
        p1 += xn * wpot[col * 2 + 1];
    }
    p0 = blk_sum256(p0, sh);
    p1 = blk_sum256(p1, sh);
    if (t == 0) {
        g_V[row] = p0 + bpot[0];
        float z = p1 + bpot[1];
        float sp = (z > 20.f) ? z : log1pf(expf(z));
        g_gamma[row] = sp + 0.1f;
    }
}

// ---------------- P-scan: per-chunk inclusive decay products ----------------
__global__ void pscan_kernel() {
    int b = blockIdx.x >> 5, c = blockIdx.x & 31;
    int t = threadIdx.x;  // 64
    int tok = b * Nseq + c * 64 + t;
    float v = g_gamma[tok] * DT_C;
    int lane = t & 31;
#pragma unroll
    for (int o = 1; o < 32; o <<= 1) {
        float n = __shfl_up_sync(0xffffffffu, v, o);
        if (lane >= o) v += n;
    }
    __shared__ float w0;
    if (t == 31) w0 = v;
    __syncthreads();
    if (t >= 32) v += w0;
    float P = expf(-v);
    g_P[tok] = P;
    g_Pinv[tok] = 1.f / P;
    if (t == 63) g_Plast[b * 32 + c] = P;
}

// ---------------- BK: parallel Mobius scan (fp64), 8 chains ----------------
struct CM {
    double r00, i00, r01, i01, r10, i10, r11, i11;
};
__device__ __forceinline__ CM cm_mul(const CM& A, const CM& B) {
    CM C;
    C.r00 = A.r00 * B.r00 - A.i00 * B.i00 + A.r01 * B.r10 - A.i01 * B.i10;
    C.i00 = A.r00 * B.i00 + A.i00 * B.r00 + A.r01 * B.i10 + A.i01 * B.r10;
    C.r01 = A.r00 * B.r01 - A.i00 * B.i01 + A.r01 * B.r11 - A.i01 * B.i11;
    C.i01 = A.r00 * B.i01 + A.i00 * B.r01 + A.r01 * B.i11 + A.i01 * B.r11;
    C.r10 = A.r10 * B.r00 - A.i10 * B.i00 + A.r11 * B.r10 - A.i11 * B.i10;
    C.i10 = A.r10 * B.i00 + A.i10 * B.r00 + A.r11 * B.i10 + A.i11 * B.r10;
    C.r11 = A.r10 * B.r01 - A.i10 * B.i01 + A.r11 * B.r11 - A.i11 * B.i11;
    C.i11 = A.r10 * B.i01 + A.i10 * B.r01 + A.r11 * B.i11 + A.i11 * B.r11;
    return C;
}
__device__ __forceinline__ void cm_norm(CM& A) {
    double m = fabs(A.r00);
    m = fmax(m, fabs(A.i00)); m = fmax(m, fabs(A.r01)); m = fmax(m, fabs(A.i01));
    m = fmax(m, fabs(A.r10)); m = fmax(m, fabs(A.i10)); m = fmax(m, fabs(A.r11));
    m = fmax(m, fabs(A.i11));
    double s = 1.0 / m;
    A.r00 *= s; A.i00 *= s; A.r01 *= s; A.i01 *= s;
    A.r10 *= s; A.i10 *= s; A.r11 *= s; A.i11 *= s;
}

__global__ void bk_scan_kernel() {
    int bb = blockIdx.x >> 1;
    int dir = blockIdx.x & 1;
    int t = threadIdx.x;  // 256, each handles 8 positions
    float* out = dir ? g_bcf : g_a;
    __shared__ CM sm[256];

    double dr[8], di[8];
    CM L;
    L.r00 = 1; L.i00 = 0; L.r01 = 0; L.i01 = 0;
    L.r10 = 0; L.i10 = 0; L.r11 = 1; L.i11 = 0;
#pragma unroll
    for (int u = 0; u < 8; u++) {
        int j = t * 8 + u;
        int pos = dir ? (Nseq - 1 - j) : j;
        int gi = bb * Nseq + pos;
        dr[u] = (double)g_V[gi] + 2.0;
        di[u] = -(double)g_gamma[gi];
        // new = M·L with M = [[d,-1],[1,0]]
        CM Nw;
        Nw.r00 = dr[u] * L.r00 - di[u] * L.i00 - L.r10;
        Nw.i00 = dr[u] * L.i00 + di[u] * L.r00 - L.i10;
        Nw.r01 = dr[u] * L.r01 - di[u] * L.i01 - L.r11;
        Nw.i01 = dr[u] * L.i01 + di[u] * L.r01 - L.i11;
        Nw.r10 = L.r00; Nw.i10 = L.i00;
        Nw.r11 = L.r01; Nw.i11 = L.i01;
        L = Nw;
    }
    cm_norm(L);
    sm[t] = L;
    __syncthreads();
    for (int off = 1; off < 256; off <<= 1) {
        CM Pm;
        bool act = (t >= off);
        if (act) Pm = sm[t - off];
        __syncthreads();
        if (act) {
            L = cm_mul(L, Pm);
            cm_norm(L);
            sm[t] = L;
        }
        __syncthreads();
    }
    // exclusive prefix
    double pr, pi, qr, qi;
    if (t == 0) {
        pr = 1; pi = 0; qr = 0; qi = 0;
    } else {
        CM E = sm[t - 1];
        pr = E.r00; pi = E.i00; qr = E.r10; qi = E.i10;
    }
#pragma unroll
    for (int u = 0; u < 8; u++) {
        int j = t * 8 + u;
        int pos = dir ? (Nseq - 1 - j) : j;
        int gi = bb * Nseq + pos;
        double npr = dr[u] * pr - di[u] * pi - qr;
        double npi = dr[u] * pi + di[u] * pr - qi;
        qr = pr; qi = pi; pr = npr; pi = npi;
        double m = fmax(fmax(fabs(pr), fabs(pi)), fmax(fabs(qr), fabs(qi)));
        double sc = 1.0 / m;
        pr *= sc; pi *= sc; qr *= sc; qi *= sc;
        double den = 1.0 / (qr * qr + qi * qi);
        out[gi * 2] = (float)((pr * qr + pi * qi) * den);
        out[gi * 2 + 1] = (float)((pi * qr - pr * qi) * den);
    }
}

// ---------------- K3: BK + residual + LN2 -> fp16 ----------------
__global__ void bk_res_ln2_kernel(const float* __restrict__ x, const float* __restrict__ wbk,
                                  const float* __restrict__ bbk, const float* __restrict__ g2,
                                  const float* __restrict__ b2) {
    int row = blockIdx.x;
    int t = threadIdx.x;
    __shared__ float sh[8];
    __shared__ float f01[2];
    if (t == 0) {
        float are = g_a[row * 2], aim = g_a[row * 2 + 1];
        float bre = g_bcf[row * 2], bim = g_bcf[row * 2 + 1];
        float drr = g_V[row] + 2.f, dii = -g_gamma[row];
        float nr = are + bre - drr, ni = aim + bim - dii;
        float inv = 1.f / (nr * nr + ni * ni);
        f01[0] = nr * inv;
        f01[1] = -ni * inv;
    }
    __syncthreads();
    float f0 = f01[0], f1 = f01[1];
    size_t base = (size_t)row * Ddim;
    float y[4];
    float s = 0.f, ss = 0.f;
#pragma unroll
    for (int j = 0; j < 4; j++) {
        int col = t * 4 + j;
        float v = x[base + col] + f0 * wbk[col] + f1 * wbk[Ddim + col] + bbk[col];
        y[j] = v;
        s += v;
        ss += v * v;
        g_x1[base + col] = v;
    }
    s = blk_sum256(s, sh);
    ss = blk_sum256(ss, sh);
    float m = s * (1.f / Ddim);
    float var = ss * (1.f / Ddim) - m * m;
    float rstd = rsqrtf(var + 1e-5f);
    __half2 h2[2];
#pragma unroll
    for (int j = 0; j < 2; j++) {
        float v0 = (y[2 * j] - m) * rstd * g2[t * 4 + 2 * j] + b2[t * 4 + 2 * j];
        float v1 = (y[2 * j + 1] - m) * rstd * g2[t * 4 + 2 * j + 1] + b2[t * 4 + 2 * j + 1];
        h2[j] = __floats2half2_rn(v0, v1);
    }
    *(uint2*)&g_xn2h[base + t * 4] = make_uint2(*(unsigned*)&h2[0], *(unsigned*)&h2[1]);
}

// ---------------- LN3 -> fp16 ----------------
__global__ void ln3_kernel(const float* __restrict__ g3, const float* __restrict__ b3) {
    int row = blockIdx.x;
    int t = threadIdx.x;
    __shared__ float sh[8];
    size_t base = (size_t)row * Ddim;
    float4 xv = *(const float4*)&g_x2[base + t * 4];
    float s = xv.x + xv.y + xv.z + xv.w;
    float ss = xv.x * xv.x + xv.y * xv.y + xv.z * xv.z + xv.w * xv.w;
    s = blk_sum256(s, sh);
    ss = blk_sum256(ss, sh);
    float m = s * (1.f / Ddim);
    float var = ss * (1.f / Ddim) - m * m;
    float rstd = rsqrtf(var + 1e-5f);
    float xa[4] = {xv.x, xv.y, xv.z, xv.w};
    __half2 h2[2];
#pragma unroll
    for (int j = 0; j < 2; j++) {
        float v0 = (xa[2 * j] - m) * rstd * g3[t * 4 + 2 * j] + b3[t * 4 + 2 * j];
        float v1 = (xa[2 * j + 1] - m) * rstd * g3[t * 4 + 2 * j + 1] + b3[t * 4 + 2 * j + 1];
        h2[j] = __floats2half2_rn(v0, v1);
    }
    *(uint2*)&g_xn3h[base + t * 4] = make_uint2(*(unsigned*)&h2[0], *(unsigned*)&h2[1]);
}

// ---------------- FP16 tensor GEMM: 128x128, 8 warps (2x4 of 64x32), K-step 32 ----------------
#define HST 40

__device__ __forceinline__ void cpa16(unsigned dst, const void* src) {
    asm volatile("cp.async.ca.shared.global [%0], [%1], 16;\n" ::"r"(dst), "l"(src));
}

// EPI: 0 = fp32 out (+Rd); 1 = gelu -> fp16; 2 = qkv scale (P/Pinv) -> fp16
template <int EPI>
__global__ __launch_bounds__(256, 2) void h16_gemm(const __half* __restrict__ A,
                                                   const __half* __restrict__ Bt,
                                                   const float* __restrict__ bias,
                                                   const float* __restrict__ Rd,
                                                   const float* __restrict__ Pv,
                                                   const float* __restrict__ Pinv,
                                                   void* __restrict__ Cv, int M, int N, int K) {
    __shared__ __half As[2][128 * HST];
    __shared__ __half Bs[2][128 * HST];
    int t = threadIdx.x;
    int warp = t >> 5, lane = t & 31;
    int gid = lane >> 2, tig = lane & 3;
    int m0 = blockIdx.y * 128, n0 = blockIdx.x * 128;
    int wm = (warp >> 2) * 64, wn = (warp & 3) * 32;

    float acc[4][4][4];
#pragma unroll
    for (int i = 0; i < 4; i++)
#pragma unroll
        for (int j = 0; j < 4; j++)
#pragma unroll
            for (int r = 0; r < 4; r++) acc[i][j][r] = 0.f;

    unsigned aBase = (unsigned)__cvta_generic_to_shared(&As[0][0]);
    unsigned bBase = (unsigned)__cvta_generic_to_shared(&Bs[0][0]);
    int r0 = t >> 2, kc0 = (t & 3) * 8;
    int r1 = (t + 256) >> 2, kc1 = ((t + 256) & 3) * 8;
    unsigned aD0 = aBase + (unsigned)(r0 * HST + kc0) * 2u;
    unsigned aD1 = aBase + (unsigned)(r1 * HST + kc1) * 2u;
    unsigned bD0 = bBase + (unsigned)(r0 * HST + kc0) * 2u;
    unsigned bD1 = bBase + (unsigned)(r1 * HST + kc1) * 2u;
    const __half* Ag0 = A + (size_t)(m0 + r0) * K + kc0;
    const __half* Ag1 = A + (size_t)(m0 + r1) * K + kc1;
    const __half* Bg0 = Bt + (size_t)(n0 + r0) * K + kc0;
    const __half* Bg1 = Bt + (size_t)(n0 + r1) * K + kc1;
    const unsigned SOFF = (unsigned)(128 * HST) * 2u;

    const int KT = K >> 5;

#define HFILL(J)                                \
    {                                           \
        int _j = (J);                           \
        unsigned so = (_j & 1) ? SOFF : 0u;     \
        int ko = _j << 5;                       \
        cpa16(aD0 + so, Ag0 + ko);              \
        cpa16(aD1 + so, Ag1 + ko);              \
        cpa16(bD0 + so, Bg0 + ko);              \
        cpa16(bD1 + so, Bg1 + ko);              \
        asm volatile("cp.async.commit_group;"); \
    }

    HFILL(0);

    for (int kt = 0; kt < KT; kt++) {
        if (kt + 1 < KT) {
            HFILL(kt + 1);
            asm volatile("cp.async.wait_group 1;");
        } else {
            asm volatile("cp.async.wait_group 0;");
        }
        __syncthreads();
        const __half* as = &As[kt & 1][0];
        const __half* bs = &Bs[kt & 1][0];
#pragma unroll
        for (int kk = 0; kk < 32; kk += 16) {
            unsigned af[4][4], bf[4][2];
#pragma unroll
            for (int mt = 0; mt < 4; mt++) {
                int rb = wm + mt * 16 + gid;
                af[mt][0] = *(const unsigned*)(as + rb * HST + kk + tig * 2);
                af[mt][1] = *(const unsigned*)(as + (rb + 8) * HST + kk + tig * 2);
                af[mt][2] = *(const unsigned*)(as + rb * HST + kk + tig * 2 + 8);
                af[mt][3] = *(const unsigned*)(as + (rb + 8) * HST + kk + tig * 2 + 8);
            }
#pragma unroll
            for (int nt = 0; nt < 4; nt++) {
                int cb = wn + nt * 8 + gid;
                bf[nt][0] = *(const unsigned*)(bs + cb * HST + kk + tig * 2);
                bf[nt][1] = *(const unsigned*)(bs + cb * HST + kk + tig * 2 + 8);
            }
#pragma unroll
            for (int mt = 0; mt < 4; mt++)
#pragma unroll
                for (int nt = 0; nt < 4; nt++) {
                    asm volatile(
                        "mma.sync.aligned.m16n8k16.row.col.f32.f16.f16.f32 "
                        "{%0,%1,%2,%3}, {%4,%5,%6,%7}, {%8,%9}, {%0,%1,%2,%3};\n"
                        : "+f"(acc[mt][nt][0]), "+f"(acc[mt][nt][1]), "+f"(acc[mt][nt][2]),
                          "+f"(acc[mt][nt][3])
                        : "r"(af[mt][0]), "r"(af[mt][1]), "r"(af[mt][2]), "r"(af[mt][3]),
                          "r"(bf[nt][0]), "r"(bf[nt][1]));
                }
        }
        __syncthreads();
    }

#pragma unroll
    for (int mt = 0; mt < 4; mt++) {
        int row = m0 + wm + mt * 16 + gid;
        float sP0 = 0.f, sPi0 = 0.f, sP8 = 0.f, sPi8 = 0.f;
        if (EPI == 2) {
            sP0 = Pv[row]; sPi0 = Pinv[row];
            sP8 = Pv[row + 8]; sPi8 = Pinv[row + 8];
        }
#pragma unroll
        for (int nt = 0; nt < 4; nt++) {
            int col = n0 + wn + nt * 8 + tig * 2;
            float b0 = bias[col], b1 = bias[col + 1];
            float v0 = acc[mt][nt][0] + b0;
            float v1 = acc[mt][nt][1] + b1;
            float v2 = acc[mt][nt][2] + b0;
            float v3 = acc[mt][nt][3] + b1;
            if (EPI == 1) {
                v0 = gelu_f(v0); v1 = gelu_f(v1); v2 = gelu_f(v2); v3 = gelu_f(v3);
                __half* C = (__half*)Cv;
                __half2 p = __floats2half2_rn(v0, v1);
                __half2 q = __floats2half2_rn(v2, v3);
                *(unsigned*)&C[(size_t)row * N + col] = *(unsigned*)&p;
                *(unsigned*)&C[(size_t)(row + 8) * N + col] = *(unsigned*)&q;
            } else if (EPI == 2) {
                float s0 = (col < 512) ? sP0 : ((col < 1024) ? sPi0 : 1.f);
                float s8 = (col < 512) ? sP8 : ((col < 1024) ? sPi8 : 1.f);
                __half* C = (__half*)Cv;
                __half2 p = __floats2half2_rn(v0 * s0, v1 * s0);
                __half2 q = __floats2half2_rn(v2 * s8, v3 * s8);
                *(unsigned*)&C[(size_t)row * N + col] = *(unsigned*)&p;
                *(unsigned*)&C[(size_t)(row + 8) * N + col] = *(unsigned*)&q;
            } else {
                float* C = (float*)Cv;
                size_t o0 = (size_t)row * N + col;
                size_t o2 = (size_t)(row + 8) * N + col;
                if (Rd != nullptr) {
                    float2 rr0 = *(const float2*)&Rd[o0];
                    float2 rr2 = *(const float2*)&Rd[o2];
                    v0 += rr0.x; v1 += rr0.y; v2 += rr2.x; v3 += rr2.y;
                }
                *(float2*)&C[o0] = make_float2(v0, v1);
                *(float2*)&C[o2] = make_float2(v2, v3);
            }
        }
    }
}

// ---------------- Hebbian chunked linear attention ----------------
__device__ __forceinline__ int ksw(int s, int d) {
    return s * 64 + (((((d >> 2) ^ (s & 15)) & 15) << 2) | (d & 3));
}
__device__ __forceinline__ int ksw4(int s, int d4) {
    return s * 64 + ((((d4 ^ (s & 15)) & 15) << 2));
}

__global__ __launch_bounds__(256) void heb_intra_kernel() {
    int bid = blockIdx.x;
    int c = bid & 31;
    int bh = bid >> 5;
    int h = bh & 7;
    int b = bh >> 3;
    int t0 = b * Nseq + c * 64;
    __shared__ float shQ[4096];
    __shared__ float shK[4096];
    __shared__ float shS[4096];
    int t = threadIdx.x;

    // load Qs, Ks (pre-scaled fp16) -> fp32 smem
    for (int idx = t; idx < 2048; idx += 256) {
        int i = idx >> 5, d2 = (idx & 31) * 2;
        size_t qb = (size_t)(t0 + i) * 1536 + h * 64 + d2;
        float2 qf = __half22float2(*(const __half2*)&g_qkvh[qb]);
        shQ[i * 64 + d2] = qf.x;
        shQ[i * 64 + d2 + 1] = qf.y;
        float2 kf = __half22float2(*(const __half2*)&g_qkvh[qb + 512]);
        shK[ksw(i, d2)] = kf.x;
        shK[ksw(i, d2 + 1)] = kf.y;
    }
    __syncthreads();

    {
        int i0 = (t >> 4) * 4, s0 = (t & 15) * 4;
        float accS[4][4];
#pragma unroll
        for (int r = 0; r < 4; r++)
#pragma unroll
            for (int q = 0; q < 4; q++) accS[r][q] = 0.f;
#pragma unroll
        for (int d4 = 0; d4 < 16; d4++) {
            float4 qa[4], ka[4];
#pragma unroll
            for (int r = 0; r < 4; r++) {
                qa[r] = *(const float4*)&shQ[(i0 + r) * 64 + d4 * 4];
                ka[r] = *(const float4*)&shK[ksw4(s0 + r, d4)];
            }
#pragma unroll
            for (int r = 0; r < 4; r++)
#pragma unroll
                for (int q = 0; q < 4; q++)
                    accS[r][q] += qa[r].x * ka[q].x + qa[r].y * ka[q].y + qa[r].z * ka[q].z +
                                  qa[r].w * ka[q].w;
        }
#pragma unroll
        for (int r = 0; r < 4; r++)
#pragma unroll
            for (int q = 0; q < 4; q++) {
                int i = i0 + r, s = s0 + q;
                shS[i * 64 + s] = (s <= i) ? ETA_C * accS[r][q] : 0.f;
            }
    }
    __syncthreads();

    // V into shQ
    for (int idx = t; idx < 2048; idx += 256) {
        int i = idx >> 5, d2 = (idx & 31) * 2;
        float2 vf =
            __half22float2(*(const __half2*)&g_qkvh[(size_t)(t0 + i) * 1536 + 1024 + h * 64 + d2]);
        shQ[i * 64 + d2] = vf.x;
        shQ[i * 64 + d2 + 1] = vf.y;
    }
    __syncthreads();

    {
        int i0 = (t >> 4) * 4, e0 = (t & 15) * 4;
        float accO[4][4];
#pragma unroll
        for (int r = 0; r < 4; r++)
#pragma unroll
            for (int q = 0; q < 4; q++) accO[r][q] = 0.f;
        for (int s = 0; s < 64; s++) {
            float4 vv = *(const float4*)&shQ[s * 64 + e0];
            float sv[4];
#pragma unroll
            for (int r = 0; r < 4; r++) sv[r] = shS[(i0 + r) * 64 + s];
#pragma unroll
            for (int r = 0; r < 4; r++) {
                accO[r][0] += sv[r] * vv.x;
                accO[r][1] += sv[r] * vv.y;
                accO[r][2] += sv[r] * vv.z;
                accO[r][3] += sv[r] * vv.w;
            }
        }
#pragma unroll
        for (int r = 0; r < 4; r++) {
            __half2 h0 = __floats2half2_rn(accO[r][0], accO[r][1]);
            __half2 h1 = __floats2half2_rn(accO[r][2], accO[r][3]);
            *(uint2*)&g_Oinh[(size_t)(t0 + i0 + r) * 512 + h * 64 + e0] =
                make_uint2(*(unsigned*)&h0, *(unsigned*)&h1);
        }
    }

    {
        int d0 = (t >> 4) * 4, e0 = (t & 15) * 4;
        float accU[4][4];
#pragma unroll
        for (int r = 0; r < 4; r++)
#pragma unroll
            for (int q = 0; q < 4; q++) accU[r][q] = 0.f;
        for (int s = 0; s < 64; s++) {
            float4 vv = *(const float4*)&shQ[s * 64 + e0];
            float kv[4];
#pragma unroll
            for (int r = 0; r < 4; r++) kv[r] = shK[ksw(s, d0 + r)];
#pragma unroll
            for (int r = 0; r < 4; r++) {
                accU[r][0] += kv[r] * vv.x;
                accU[r][1] += kv[r] * vv.y;
                accU[r][2] += kv[r] * vv.z;
                accU[r][3] += kv[r] * vv.w;
            }
        }
        size_t ub = ((size_t)bh * 32 + c) * 4096;
#pragma unroll
        for (int r = 0; r < 4; r++) {
            float4 u4 = make_float4(accU[r][0], accU[r][1], accU[r][2], accU[r][3]);
            *(float4*)&g_U[ub + (d0 + r) * 64 + e0] = u4;
        }
    }
}

__global__ void heb_state_kernel() {
    int bh = blockIdx.x;
    int b = bh >> 3;
    int t = threadIdx.x;
    float4 W[4];
#pragma unroll
    for (int j = 0; j < 4; j++) W[j] = make_float4(0.f, 0.f, 0.f, 0.f);
    for (int c = 0; c < 32; c++) {
        size_t off = ((size_t)bh * 32 + c) * 4096 + t * 16;
        float pl = g_Plast[b * 32 + c];
#pragma unroll
        for (int j = 0; j < 4; j++) {
            float4 u = *(const float4*)&g_U[off + j * 4];
            *(float4*)&g_Wst[off + j * 4] = W[j];
            W[j].x = pl * (W[j].x + ETA_C * u.x);
            W[j].y = pl * (W[j].y + ETA_C * u.y);
            W[j].z = pl * (W[j].z + ETA_C * u.z);
            W[j].w = pl * (W[j].w + ETA_C * u.w);
        }
    }
}

__global__ __launch_bounds__(256) void heb_inter_kernel() {
    int bid = blockIdx.x;
    int c = bid & 31;
    int bh = bid >> 5;
    int h = bh & 7;
    int b = bh >> 3;
    int t0 = b * Nseq + c * 64;
    __shared__ float shQ2[4096];
    __shared__ float shW[4096];
    int t = threadIdx.x;
    size_t wb = ((size_t)bh * 32 + c) * 4096;
    for (int idx = t; idx < 2048; idx += 256) {
        int i = idx >> 5, d2 = (idx & 31) * 2;
        float2 qf =
            __half22float2(*(const __half2*)&g_qkvh[(size_t)(t0 + i) * 1536 + h * 64 + d2]);
        shQ2[i * 64 + d2] = qf.x;
        shQ2[i * 64 + d2 + 1] = qf.y;
    }
    for (int idx = t; idx < 4096; idx += 256) shW[idx] = g_Wst[wb + idx];
    __syncthreads();
    int i0 = (t >> 4) * 4, e0 = (t & 15) * 4;
    float acc[4][4];
#pragma unroll
    for (int r = 0; r < 4; r++) {
        float2 o0 =
            __half22float2(*(const __half2*)&g_Oinh[(size_t)(t0 + i0 + r) * 512 + h * 64 + e0]);
        float2 o1 = __half22float2(
            *(const __half2*)&g_Oinh[(size_t)(t0 + i0 + r) * 512 + h * 64 + e0 + 2]);
        acc[r][0] = o0.x; acc[r][1] = o0.y; acc[r][2] = o1.x; acc[r][3] = o1.y;
    }
    for (int d = 0; d < 64; d++) {
        float4 wv = *(const float4*)&shW[d * 64 + e0];
        float qv[4];
#pragma unroll
        for (int r = 0; r < 4; r++) qv[r] = shQ2[(i0 + r) * 64 + d];
#pragma unroll
        for (int r = 0; r < 4; r++) {
            acc[r][0] += qv[r] * wv.x;
            acc[r][1] += qv[r] * wv.y;
            acc[r][2] += qv[r] * wv.z;
            acc[r][3] += qv[r] * wv.w;
        }
    }
#pragma unroll
    for (int r = 0; r < 4; r++) {
        __half2 h0 = __floats2half2_rn(acc[r][0], acc[r][1]);
        __half2 h1 = __floats2half2_rn(acc[r][2], acc[r][3]);
        *(uint2*)&g_hebh[(size_t)(t0 + i0 + r) * 512 + h * 64 + e0] =
            make_uint2(*(unsigned*)&h0, *(unsigned*)&h1);
    }
}

// ---------------- launch ----------------
extern "C" void kernel_launch(void* const* d_in, const int* in_sizes, int n_in,
                              void* d_out, int out_size) {
    const float* x     = (const float*)d_in[0];
    const float* ln1_g = (const float*)d_in[1];
    const float* ln1_b = (const float*)d_in[2];
    const float* ln2_g = (const float*)d_in[3];
    const float* ln2_b = (const float*)d_in[4];
    const float* ln3_g = (const float*)d_in[5];
    const float* ln3_b = (const float*)d_in[6];
    const float* w_pot = (const float*)d_in[7];
    const float* b_pot = (const float*)d_in[8];
    const float* w_bk  = (const float*)d_in[9];
    const float* b_bk  = (const float*)d_in[10];
    const float* w_qkv = (const float*)d_in[11];
    const float* b_qkv = (const float*)d_in[12];
    const float* w_out = (const float*)d_in[13];
    const float* b_out = (const float*)d_in[14];
    const float* w_ff1 = (const float*)d_in[15];
    const float* b_ff1 = (const float*)d_in[16];
    const float* w_ff2 = (const float*)d_in[17];
    const float* b_ff2 = (const float*)d_in[18];
    float* out = (float*)d_out;

    float *p_x1, *p_x2, *p_P, *p_Pinv;
    __half *p_qkvh, *p_xn2h, *p_xn3h, *p_hebh, *p_ffh, *p_wqt, *p_wot, *p_w1t, *p_w2t;
    cudaGetSymbolAddress((void**)&p_x1, g_x1);
    cudaGetSymbolAddress((void**)&p_x2, g_x2);
    cudaGetSymbolAddress((void**)&p_P, g_P);
    cudaGetSymbolAddress((void**)&p_Pinv, g_Pinv);
    cudaGetSymbolAddress((void**)&p_qkvh, g_qkvh);
    cudaGetSymbolAddress((void**)&p_xn2h, g_xn2h);
    cudaGetSymbolAddress((void**)&p_xn3h, g_xn3h);
    cudaGetSymbolAddress((void**)&p_hebh, g_hebh);
    cudaGetSymbolAddress((void**)&p_ffh, g_ffh);
    cudaGetSymbolAddress((void**)&p_wqt, g_wqt);
    cudaGetSymbolAddress((void**)&p_wot, g_wot);
    cudaGetSymbolAddress((void**)&p_w1t, g_w1t);
    cudaGetSymbolAddress((void**)&p_w2t, g_w2t);

    conv_wh_kernel<<<dim3(1536 / 32, 1024 / 32), 256>>>(w_qkv, p_wqt, 1024, 1536);
    conv_wh_kernel<<<dim3(1024 / 32, 512 / 32), 256>>>(w_out, p_wot, 512, 1024);
    conv_wh_kernel<<<dim3(4096 / 32, 1024 / 32), 256>>>(w_ff1, p_w1t, 1024, 4096);
    conv_wh_kernel<<<dim3(1024 / 32, 4096 / 32), 256>>>(w_ff2, p_w2t, 4096, 1024);

    ln1_pot_kernel<<<Ttok, 256>>>(x, ln1_g, ln1_b, w_pot, b_pot);
    pscan_kernel<<<128, 64>>>();
    bk_scan_kernel<<<8, 256>>>();
    bk_res_ln2_kernel<<<Ttok, 256>>>(x, w_bk, b_bk, ln2_g, ln2_b);
    h16_gemm<2><<<dim3(12, 64), 256>>>(p_xn2h, p_wqt, b_qkv, nullptr, p_P, p_Pinv, p_qkvh, Ttok,
                                       1536, 1024);
    heb_intra_kernel<<<1024, 256>>>();
    heb_state_kernel<<<32, 256>>>();
    heb_inter_kernel<<<1024, 256>>>();
    h16_gemm<0><<<dim3(8, 64), 256>>>(p_hebh, p_wot, b_out, p_x1, nullptr, nullptr, p_x2, Ttok,
                                      1024, 512);
    ln3_kernel<<<Ttok, 256>>>(ln3_g, ln3_b);
    h16_gemm<1><<<dim3(32, 64), 256>>>(p_xn3h, p_w1t, b_ff1, nullptr, nullptr, nullptr, p_ffh,
                                       Ttok, 4096, 1024);
    h16_gemm<0><<<dim3(8, 64), 256>>>(p_ffh, p_w2t, b_ff2, p_x2, nullptr, nullptr, out, Ttok,
                                      1024, 4096);
}

// round 14
// speedup vs baseline: 1.8972x; 1.0677x over previous
#include <cuda_runtime.h>
#include <cuda_fp16.h>
#include <stdint.h>
#include <math.h>

#define Bdim 4
#define Nseq 2048
#define Ddim 1024
#define FFd  4096
#define Ttok 8192
#define ETA_C 0.1f
#define DT_C  0.01f

// ---------------- scratch ----------------
__device__ float g_V[Ttok];
__device__ float g_gamma[Ttok];
__device__ float g_a[Ttok * 2];
__device__ float g_bcf[Ttok * 2];
__device__ float g_P[Ttok];
__device__ float g_Pinv[Ttok];
__device__ float g_Plast[Bdim * 32];
__device__ float g_x1[(size_t)Ttok * Ddim];
__device__ float g_U[32 * 32 * 4096];
__device__ float g_Wst[32 * 32 * 4096];
__device__ float g_x2[(size_t)Ttok * Ddim];
// fp16 activations
__device__ __half g_qkvh[(size_t)Ttok * 1536];   // [q*P | k/P | v]
__device__ __half g_Oinh[(size_t)Ttok * 512];
__device__ __half g_xn2h[(size_t)Ttok * Ddim];
__device__ __half g_xn3h[(size_t)Ttok * Ddim];
__device__ __half g_hebh[(size_t)Ttok * 512];
__device__ __half g_ffh[(size_t)Ttok * FFd];
// fp16 transposed weights [N][K]
__device__ __half g_wqt[(size_t)1536 * Ddim];
__device__ __half g_wot[(size_t)Ddim * 512];
__device__ __half g_w1t[(size_t)FFd * Ddim];
__device__ __half g_w2t[(size_t)Ddim * FFd];

// ---------------- helpers ----------------
__device__ __forceinline__ float blk_sum256(float v, float* sh) {
    int t = threadIdx.x;
#pragma unroll
    for (int o = 16; o > 0; o >>= 1) v += __shfl_down_sync(0xffffffffu, v, o);
    if ((t & 31) == 0) sh[t >> 5] = v;
    __syncthreads();
    if (t < 32) {
        float r = (t < 8) ? sh[t] : 0.f;
#pragma unroll
        for (int o = 4; o > 0; o >>= 1) r += __shfl_down_sync(0xffffffffu, r, o);
        if (t == 0) sh[0] = r;
    }
    __syncthreads();
    float r = sh[0];
    __syncthreads();
    return r;
}

__device__ __forceinline__ float gelu_f(float x) {
    float x3 = x * x * x;
    float u = 0.7978845608028654f * (x + 0.044715f * x3);
    return 0.5f * x * (1.f + tanhf(u));
}

#define MMA16(C0, C1, C2, C3, A0, A1, A2, A3, B0, B1)                                     \
    asm volatile(                                                                         \
        "mma.sync.aligned.m16n8k16.row.col.f32.f16.f16.f32 "                              \
        "{%0,%1,%2,%3}, {%4,%5,%6,%7}, {%8,%9}, {%0,%1,%2,%3};\n"                         \
        : "+f"(C0), "+f"(C1), "+f"(C2), "+f"(C3)                                          \
        : "r"(A0), "r"(A1), "r"(A2), "r"(A3), "r"(B0), "r"(B1))

// ---------------- weight transpose to fp16 [N][K] ----------------
__global__ void conv_wh_kernel(const float* __restrict__ W, __half* __restrict__ out, int K,
                               int N) {
    __shared__ float tile[32][33];
    int t = threadIdx.x;
    int tx = t & 31, ty = t >> 5;
    int n0 = blockIdx.x * 32, k0 = blockIdx.y * 32;
#pragma unroll
    for (int r = 0; r < 4; r++)
        tile[ty + r * 8][tx] = W[(size_t)(k0 + ty + r * 8) * N + n0 + tx];
    __syncthreads();
#pragma unroll
    for (int r = 0; r < 4; r++)
        out[(size_t)(n0 + ty + r * 8) * K + k0 + tx] = __float2half(tile[tx][ty + r * 8]);
}

// ---------------- K1: LN1 + potential ----------------
__global__ void ln1_pot_kernel(const float* __restrict__ x, const float* __restrict__ g1,
                               const float* __restrict__ b1, const float* __restrict__ wpot,
                               const float* __restrict__ bpot) {
    int row = blockIdx.x;
    int t = threadIdx.x;
    __shared__ float sh[8];
    const float4* xr = (const float4*)(x + (size_t)row * Ddim);
    float4 xv = xr[t];
    float s = xv.x + xv.y + xv.z + xv.w;
    float ss = xv.x * xv.x + xv.y * xv.y + xv.z * xv.z + xv.w * xv.w;
    s = blk_sum256(s, sh);
    ss = blk_sum256(ss, sh);
    float m = s * (1.f / Ddim);
    float var = ss * (1.f / Ddim) - m * m;
    float rstd = rsqrtf(var + 1e-5f);
    float xa[4] = {xv.x, xv.y, xv.z, xv.w};
    float p0 = 0.f, p1 = 0.f;
#pragma unroll
    for (int j = 0; j < 4; j++) {
        int col = t * 4 + j;
        float xn = (xa[j] - m) * rstd * g1[col] + b1[col];
        p0 += xn * wpot[col * 2];
        p1 += xn * wpot[col * 2 + 1];
    }
    p0 = blk_sum256(p0, sh);
    p1 = blk_sum256(p1, sh);
    if (t == 0) {
        g_V[row] = p0 + bpot[0];
        float z = p1 + bpot[1];
        float sp = (z > 20.f) ? z : log1pf(expf(z));
        g_gamma[row] = sp + 0.1f;
    }
}

// ---------------- P-scan ----------------
__global__ void pscan_kernel() {
    int b = blockIdx.x >> 5, c = blockIdx.x & 31;
    int t = threadIdx.x;  // 64
    int tok = b * Nseq + c * 64 + t;
    float v = g_gamma[tok] * DT_C;
    int lane = t & 31;
#pragma unroll
    for (int o = 1; o < 32; o <<= 1) {
        float n = __shfl_up_sync(0xffffffffu, v, o);
        if (lane >= o) v += n;
    }
    __shared__ float w0;
    if (t == 31) w0 = v;
    __syncthreads();
    if (t >= 32) v += w0;
    float P = expf(-v);
    g_P[tok] = P;
    g_Pinv[tok] = 1.f / P;
    if (t == 63) g_Plast[b * 32 + c] = P;
}

// ---------------- BK: parallel Mobius scan (fp64) ----------------
struct CM {
    double r00, i00, r01, i01, r10, i10, r11, i11;
};
__device__ __forceinline__ CM cm_mul(const CM& A, const CM& B) {
    CM C;
    C.r00 = A.r00 * B.r00 - A.i00 * B.i00 + A.r01 * B.r10 - A.i01 * B.i10;
    C.i00 = A.r00 * B.i00 + A.i00 * B.r00 + A.r01 * B.i10 + A.i01 * B.r10;
    C.r01 = A.r00 * B.r01 - A.i00 * B.i01 + A.r01 * B.r11 - A.i01 * B.i11;
    C.i01 = A.r00 * B.i01 + A.i00 * B.r01 + A.r01 * B.i11 + A.i01 * B.r11;
    C.r10 = A.r10 * B.r00 - A.i10 * B.i00 + A.r11 * B.r10 - A.i11 * B.i10;
    C.i10 = A.r10 * B.i00 + A.i10 * B.r00 + A.r11 * B.i10 + A.i11 * B.r10;
    C.r11 = A.r10 * B.r01 - A.i10 * B.i01 + A.r11 * B.r11 - A.i11 * B.i11;
    C.i11 = A.r10 * B.i01 + A.i10 * B.r01 + A.r11 * B.i11 + A.i11 * B.r11;
    return C;
}
__device__ __forceinline__ void cm_norm(CM& A) {
    double m = fabs(A.r00);
    m = fmax(m, fabs(A.i00)); m = fmax(m, fabs(A.r01)); m = fmax(m, fabs(A.i01));
    m = fmax(m, fabs(A.r10)); m = fmax(m, fabs(A.i10)); m = fmax(m, fabs(A.r11));
    m = fmax(m, fabs(A.i11));
    double s = 1.0 / m;
    A.r00 *= s; A.i00 *= s; A.r01 *= s; A.i01 *= s;
    A.r10 *= s; A.i10 *= s; A.r11 *= s; A.i11 *= s;
}

__global__ void bk_scan_kernel() {
    int bb = blockIdx.x >> 1;
    int dir = blockIdx.x & 1;
    int t = threadIdx.x;
    float* out = dir ? g_bcf : g_a;
    __shared__ CM sm[256];

    double dr[8], di[8];
    CM L;
    L.r00 = 1; L.i00 = 0; L.r01 = 0; L.i01 = 0;
    L.r10 = 0; L.i10 = 0; L.r11 = 1; L.i11 = 0;
#pragma unroll
    for (int u = 0; u < 8; u++) {
        int j = t * 8 + u;
        int pos = dir ? (Nseq - 1 - j) : j;
        int gi = bb * Nseq + pos;
        dr[u] = (double)g_V[gi] + 2.0;
        di[u] = -(double)g_gamma[gi];
        CM Nw;
        Nw.r00 = dr[u] * L.r00 - di[u] * L.i00 - L.r10;
        Nw.i00 = dr[u] * L.i00 + di[u] * L.r00 - L.i10;
        Nw.r01 = dr[u] * L.r01 - di[u] * L.i01 - L.r11;
        Nw.i01 = dr[u] * L.i01 + di[u] * L.r01 - L.i11;
        Nw.r10 = L.r00; Nw.i10 = L.i00;
        Nw.r11 = L.r01; Nw.i11 = L.i01;
        L = Nw;
    }
    cm_norm(L);
    sm[t] = L;
    __syncthreads();
    for (int off = 1; off < 256; off <<= 1) {
        CM Pm;
        bool act = (t >= off);
        if (act) Pm = sm[t - off];
        __syncthreads();
        if (act) {
            L = cm_mul(L, Pm);
            cm_norm(L);
            sm[t] = L;
        }
        __syncthreads();
    }
    double pr, pi, qr, qi;
    if (t == 0) {
        pr = 1; pi = 0; qr = 0; qi = 0;
    } else {
        CM E = sm[t - 1];
        pr = E.r00; pi = E.i00; qr = E.r10; qi = E.i10;
    }
#pragma unroll
    for (int u = 0; u < 8; u++) {
        int j = t * 8 + u;
        int pos = dir ? (Nseq - 1 - j) : j;
        int gi = bb * Nseq + pos;
        double npr = dr[u] * pr - di[u] * pi - qr;
        double npi = dr[u] * pi + di[u] * pr - qi;
        qr = pr; qi = pi; pr = npr; pi = npi;
        double m = fmax(fmax(fabs(pr), fabs(pi)), fmax(fabs(qr), fabs(qi)));
        double sc = 1.0 / m;
        pr *= sc; pi *= sc; qr *= sc; qi *= sc;
        double den = 1.0 / (qr * qr + qi * qi);
        out[gi * 2] = (float)((pr * qr + pi * qi) * den);
        out[gi * 2 + 1] = (float)((pi * qr - pr * qi) * den);
    }
}

// ---------------- K3: BK + residual + LN2 -> fp16 ----------------
__global__ void bk_res_ln2_kernel(const float* __restrict__ x, const float* __restrict__ wbk,
                                  const float* __restrict__ bbk, const float* __restrict__ g2,
                                  const float* __restrict__ b2) {
    int row = blockIdx.x;
    int t = threadIdx.x;
    __shared__ float sh[8];
    __shared__ float f01[2];
    if (t == 0) {
        float are = g_a[row * 2], aim = g_a[row * 2 + 1];
        float bre = g_bcf[row * 2], bim = g_bcf[row * 2 + 1];
        float drr = g_V[row] + 2.f, dii = -g_gamma[row];
        float nr = are + bre - drr, ni = aim + bim - dii;
        float inv = 1.f / (nr * nr + ni * ni);
        f01[0] = nr * inv;
        f01[1] = -ni * inv;
    }
    __syncthreads();
    float f0 = f01[0], f1 = f01[1];
    size_t base = (size_t)row * Ddim;
    float y[4];
    float s = 0.f, ss = 0.f;
#pragma unroll
    for (int j = 0; j < 4; j++) {
        int col = t * 4 + j;
        float v = x[base + col] + f0 * wbk[col] + f1 * wbk[Ddim + col] + bbk[col];
        y[j] = v;
        s += v;
        ss += v * v;
        g_x1[base + col] = v;
    }
    s = blk_sum256(s, sh);
    ss = blk_sum256(ss, sh);
    float m = s * (1.f / Ddim);
    float var = ss * (1.f / Ddim) - m * m;
    float rstd = rsqrtf(var + 1e-5f);
    __half2 h2[2];
#pragma unroll
    for (int j = 0; j < 2; j++) {
        float v0 = (y[2 * j] - m) * rstd * g2[t * 4 + 2 * j] + b2[t * 4 + 2 * j];
        float v1 = (y[2 * j + 1] - m) * rstd * g2[t * 4 + 2 * j + 1] + b2[t * 4 + 2 * j + 1];
        h2[j] = __floats2half2_rn(v0, v1);
    }
    *(uint2*)&g_xn2h[base + t * 4] = make_uint2(*(unsigned*)&h2[0], *(unsigned*)&h2[1]);
}

// ---------------- LN3 -> fp16 ----------------
__global__ void ln3_kernel(const float* __restrict__ g3, const float* __restrict__ b3) {
    int row = blockIdx.x;
    int t = threadIdx.x;
    __shared__ float sh[8];
    size_t base = (size_t)row * Ddim;
    float4 xv = *(const float4*)&g_x2[base + t * 4];
    float s = xv.x + xv.y + xv.z + xv.w;
    float ss = xv.x * xv.x + xv.y * xv.y + xv.z * xv.z + xv.w * xv.w;
    s = blk_sum256(s, sh);
    ss = blk_sum256(ss, sh);
    float m = s * (1.f / Ddim);
    float var = ss * (1.f / Ddim) - m * m;
    float rstd = rsqrtf(var + 1e-5f);
    float xa[4] = {xv.x, xv.y, xv.z, xv.w};
    __half2 h2[2];
#pragma unroll
    for (int j = 0; j < 2; j++) {
        float v0 = (xa[2 * j] - m) * rstd * g3[t * 4 + 2 * j] + b3[t * 4 + 2 * j];
        float v1 = (xa[2 * j + 1] - m) * rstd * g3[t * 4 + 2 * j + 1] + b3[t * 4 + 2 * j + 1];
        h2[j] = __floats2half2_rn(v0, v1);
    }
    *(uint2*)&g_xn3h[base + t * 4] = make_uint2(*(unsigned*)&h2[0], *(unsigned*)&h2[1]);
}

// ---------------- FP16 tensor GEMM: 128x128, 8 warps, K-step 32 ----------------
#define HST 40

__device__ __forceinline__ void cpa16(unsigned dst, const void* src) {
    asm volatile("cp.async.ca.shared.global [%0], [%1], 16;\n" ::"r"(dst), "l"(src));
}

// EPI: 0 = fp32 out (+Rd); 1 = gelu -> fp16; 2 = qkv scale -> fp16
template <int EPI>
__global__ __launch_bounds__(256, 2) void h16_gemm(const __half* __restrict__ A,
                                                   const __half* __restrict__ Bt,
                                                   const float* __restrict__ bias,
                                                   const float* __restrict__ Rd,
                                                   const float* __restrict__ Pv,
                                                   const float* __restrict__ Pinv,
                                                   void* __restrict__ Cv, int M, int N, int K) {
    __shared__ __half As[2][128 * HST];
    __shared__ __half Bs[2][128 * HST];
    int t = threadIdx.x;
    int warp = t >> 5, lane = t & 31;
    int gid = lane >> 2, tig = lane & 3;
    int m0 = blockIdx.y * 128, n0 = blockIdx.x * 128;
    int wm = (warp >> 2) * 64, wn = (warp & 3) * 32;

    float acc[4][4][4];
#pragma unroll
    for (int i = 0; i < 4; i++)
#pragma unroll
        for (int j = 0; j < 4; j++)
#pragma unroll
            for (int r = 0; r < 4; r++) acc[i][j][r] = 0.f;

    unsigned aBase = (unsigned)__cvta_generic_to_shared(&As[0][0]);
    unsigned bBase = (unsigned)__cvta_generic_to_shared(&Bs[0][0]);
    int r0 = t >> 2, kc0 = (t & 3) * 8;
    int r1 = (t + 256) >> 2, kc1 = ((t + 256) & 3) * 8;
    unsigned aD0 = aBase + (unsigned)(r0 * HST + kc0) * 2u;
    unsigned aD1 = aBase + (unsigned)(r1 * HST + kc1) * 2u;
    unsigned bD0 = bBase + (unsigned)(r0 * HST + kc0) * 2u;
    unsigned bD1 = bBase + (unsigned)(r1 * HST + kc1) * 2u;
    const __half* Ag0 = A + (size_t)(m0 + r0) * K + kc0;
    const __half* Ag1 = A + (size_t)(m0 + r1) * K + kc1;
    const __half* Bg0 = Bt + (size_t)(n0 + r0) * K + kc0;
    const __half* Bg1 = Bt + (size_t)(n0 + r1) * K + kc1;
    const unsigned SOFF = (unsigned)(128 * HST) * 2u;

    const int KT = K >> 5;

#define HFILL(J)                                \
    {                                           \
        int _j = (J);                           \
        unsigned so = (_j & 1) ? SOFF : 0u;     \
        int ko = _j << 5;                       \
        cpa16(aD0 + so, Ag0 + ko);              \
        cpa16(aD1 + so, Ag1 + ko);              \
        cpa16(bD0 + so, Bg0 + ko);              \
        cpa16(bD1 + so, Bg1 + ko);              \
        asm volatile("cp.async.commit_group;"); \
    }

    HFILL(0);

    for (int kt = 0; kt < KT; kt++) {
        if (kt + 1 < KT) {
            HFILL(kt + 1);
            asm volatile("cp.async.wait_group 1;");
        } else {
            asm volatile("cp.async.wait_group 0;");
        }
        __syncthreads();
        const __half* as = &As[kt & 1][0];
        const __half* bs = &Bs[kt & 1][0];
#pragma unroll
        for (int kk = 0; kk < 32; kk += 16) {
            unsigned af[4][4], bf[4][2];
#pragma unroll
            for (int mt = 0; mt < 4; mt++) {
                int rb = wm + mt * 16 + gid;
                af[mt][0] = *(const unsigned*)(as + rb * HST + kk + tig * 2);
                af[mt][1] = *(const unsigned*)(as + (rb + 8) * HST + kk + tig * 2);
                af[mt][2] = *(const unsigned*)(as + rb * HST + kk + tig * 2 + 8);
                af[mt][3] = *(const unsigned*)(as + (rb + 8) * HST + kk + tig * 2 + 8);
            }
#pragma unroll
            for (int nt = 0; nt < 4; nt++) {
                int cb = wn + nt * 8 + gid;
                bf[nt][0] = *(const unsigned*)(bs + cb * HST + kk + tig * 2);
                bf[nt][1] = *(const unsigned*)(bs + cb * HST + kk + tig * 2 + 8);
            }
#pragma unroll
            for (int mt = 0; mt < 4; mt++)
#pragma unroll
                for (int nt = 0; nt < 4; nt++)
                    MMA16(acc[mt][nt][0], acc[mt][nt][1], acc[mt][nt][2], acc[mt][nt][3],
                          af[mt][0], af[mt][1], af[mt][2], af[mt][3], bf[nt][0], bf[nt][1]);
        }
        __syncthreads();
    }

#pragma unroll
    for (int mt = 0; mt < 4; mt++) {
        int row = m0 + wm + mt * 16 + gid;
        float sP0 = 0.f, sPi0 = 0.f, sP8 = 0.f, sPi8 = 0.f;
        if (EPI == 2) {
            sP0 = Pv[row]; sPi0 = Pinv[row];
            sP8 = Pv[row + 8]; sPi8 = Pinv[row + 8];
        }
#pragma unroll
        for (int nt = 0; nt < 4; nt++) {
            int col = n0 + wn + nt * 8 + tig * 2;
            float b0 = bias[col], b1 = bias[col + 1];
            float v0 = acc[mt][nt][0] + b0;
            float v1 = acc[mt][nt][1] + b1;
            float v2 = acc[mt][nt][2] + b0;
            float v3 = acc[mt][nt][3] + b1;
            if (EPI == 1) {
                v0 = gelu_f(v0); v1 = gelu_f(v1); v2 = gelu_f(v2); v3 = gelu_f(v3);
                __half* C = (__half*)Cv;
                __half2 p = __floats2half2_rn(v0, v1);
                __half2 q = __floats2half2_rn(v2, v3);
                *(unsigned*)&C[(size_t)row * N + col] = *(unsigned*)&p;
                *(unsigned*)&C[(size_t)(row + 8) * N + col] = *(unsigned*)&q;
            } else if (EPI == 2) {
                float s0 = (col < 512) ? sP0 : ((col < 1024) ? sPi0 : 1.f);
                float s8 = (col < 512) ? sP8 : ((col < 1024) ? sPi8 : 1.f);
                __half* C = (__half*)Cv;
                __half2 p = __floats2half2_rn(v0 * s0, v1 * s0);
                __half2 q = __floats2half2_rn(v2 * s8, v3 * s8);
                *(unsigned*)&C[(size_t)row * N + col] = *(unsigned*)&p;
                *(unsigned*)&C[(size_t)(row + 8) * N + col] = *(unsigned*)&q;
            } else {
                float* C = (float*)Cv;
                size_t o0 = (size_t)row * N + col;
                size_t o2 = (size_t)(row + 8) * N + col;
                if (Rd != nullptr) {
                    float2 rr0 = *(const float2*)&Rd[o0];
                    float2 rr2 = *(const float2*)&Rd[o2];
                    v0 += rr0.x; v1 += rr0.y; v2 += rr2.x; v3 += rr2.y;
                }
                *(float2*)&C[o0] = make_float2(v0, v1);
                *(float2*)&C[o2] = make_float2(v2, v3);
            }
        }
    }
}

// ---------------- Hebbian intra: tensor-core S/O/U ----------------
// Per block (bh, chunk): S = Q·K^T (masked, eta), O = S·V, U = K^T·V. 4 warps.
__global__ __launch_bounds__(128) void heb_intra_tc() {
    int bid = blockIdx.x;
    int c = bid & 31;
    int bh = bid >> 5;
    int h = bh & 7;
    int b = bh >> 3;
    int t0 = b * Nseq + c * 64;
    __shared__ __half Q[64 * 72];
    __shared__ __half K[64 * 72];
    __shared__ __half Kt[64 * 66];
    __shared__ __half Vt[64 * 66];
    int t = threadIdx.x;
    int warp = t >> 5, lane = t & 31;
    int gid = lane >> 2, tig = lane & 3;

    // fill: Q,K row-major [i][d]; Kt,Vt transposed [d][i]
    for (int idx = t; idx < 2048; idx += 128) {
        int i = idx >> 5, d2 = (idx & 31) * 2;
        size_t qb = (size_t)(t0 + i) * 1536 + h * 64 + d2;
        *(unsigned*)&Q[i * 72 + d2] = *(const unsigned*)&g_qkvh[qb];
        __half2 kh = *(const __half2*)&g_qkvh[qb + 512];
        *(__half2*)&K[i * 72 + d2] = kh;
        Kt[d2 * 66 + i] = __low2half(kh);
        Kt[(d2 + 1) * 66 + i] = __high2half(kh);
        __half2 vh = *(const __half2*)&g_qkvh[qb + 1024];
        Vt[d2 * 66 + i] = __low2half(vh);
        Vt[(d2 + 1) * 66 + i] = __high2half(vh);
    }
    __syncthreads();

    int wrow = warp * 16;

    // ---- S = Q·K^T (M=64 rows split by warp, N=64, K=64) ----
    float sc[8][4];
#pragma unroll
    for (int nt = 0; nt < 8; nt++)
#pragma unroll
        for (int r = 0; r < 4; r++) sc[nt][r] = 0.f;
#pragma unroll
    for (int kt = 0; kt < 4; kt++) {
        int kk = kt * 16;
        unsigned a0 = *(const unsigned*)&Q[(wrow + gid) * 72 + kk + tig * 2];
        unsigned a1 = *(const unsigned*)&Q[(wrow + gid + 8) * 72 + kk + tig * 2];
        unsigned a2 = *(const unsigned*)&Q[(wrow + gid) * 72 + kk + tig * 2 + 8];
        unsigned a3 = *(const unsigned*)&Q[(wrow + gid + 8) * 72 + kk + tig * 2 + 8];
#pragma unroll
        for (int nt = 0; nt < 8; nt++) {
            unsigned b0 = *(const unsigned*)&K[(nt * 8 + gid) * 72 + kk + tig * 2];
            unsigned b1 = *(const unsigned*)&K[(nt * 8 + gid) * 72 + kk + tig * 2 + 8];
            MMA16(sc[nt][0], sc[nt][1], sc[nt][2], sc[nt][3], a0, a1, a2, a3, b0, b1);
        }
    }
    // mask + eta, pack to fp16 a-frag form (kept in registers)
    unsigned apk[8][2];
    {
        int i0 = wrow + gid, i8 = i0 + 8;
#pragma unroll
        for (int nt = 0; nt < 8; nt++) {
            int s0 = nt * 8 + tig * 2;
            float v0 = (s0 <= i0) ? ETA_C * sc[nt][0] : 0.f;
            float v1 = (s0 + 1 <= i0) ? ETA_C * sc[nt][1] : 0.f;
            float v2 = (s0 <= i8) ? ETA_C * sc[nt][2] : 0.f;
            float v3 = (s0 + 1 <= i8) ? ETA_C * sc[nt][3] : 0.f;
            __half2 p = __floats2half2_rn(v0, v1);
            __half2 q = __floats2half2_rn(v2, v3);
            apk[nt][0] = *(unsigned*)&p;
            apk[nt][1] = *(unsigned*)&q;
        }
    }
    // ---- O = S·V (B from Vt) ----
    {
        float oc[8][4];
#pragma unroll
        for (int nt = 0; nt < 8; nt++)
#pragma unroll
            for (int r = 0; r < 4; r++) oc[nt][r] = 0.f;
#pragma unroll
        for (int kt = 0; kt < 4; kt++) {
            int kk = kt * 16;
            unsigned a0 = apk[2 * kt][0], a1 = apk[2 * kt][1];
            unsigned a2 = apk[2 * kt + 1][0], a3 = apk[2 * kt + 1][1];
#pragma unroll
            for (int nt = 0; nt < 8; nt++) {
                unsigned b0 = *(const unsigned*)&Vt[(nt * 8 + gid) * 66 + kk + tig * 2];
                unsigned b1 = *(const unsigned*)&Vt[(nt * 8 + gid) * 66 + kk + tig * 2 + 8];
                MMA16(oc[nt][0], oc[nt][1], oc[nt][2], oc[nt][3], a0, a1, a2, a3, b0, b1);
            }
        }
        int i0 = t0 + wrow + gid;
#pragma unroll
        for (int nt = 0; nt < 8; nt++) {
            int col = h * 64 + nt * 8 + tig * 2;
            __half2 p = __floats2half2_rn(oc[nt][0], oc[nt][1]);
            __half2 q = __floats2half2_rn(oc[nt][2], oc[nt][3]);
            *(unsigned*)&g_Oinh[(size_t)i0 * 512 + col] = *(unsigned*)&p;
            *(unsigned*)&g_Oinh[(size_t)(i0 + 8) * 512 + col] = *(unsigned*)&q;
        }
    }
    // ---- U = K^T·V (A from Kt, B from Vt) ----
    {
        float uc[8][4];
#pragma unroll
        for (int nt = 0; nt < 8; nt++)
#pragma unroll
            for (int r = 0; r < 4; r++) uc[nt][r] = 0.f;
#pragma unroll
        for (int kt = 0; kt < 4; kt++) {
            int kk = kt * 16;
            unsigned a0 = *(const unsigned*)&Kt[(wrow + gid) * 66 + kk + tig * 2];
            unsigned a1 = *(const unsigned*)&Kt[(wrow + gid + 8) * 66 + kk + tig * 2];
            unsigned a2 = *(const unsigned*)&Kt[(wrow + gid) * 66 + kk + tig * 2 + 8];
            unsigned a3 = *(const unsigned*)&Kt[(wrow + gid + 8) * 66 + kk + tig * 2 + 8];
#pragma unroll
            for (int nt = 0; nt < 8; nt++) {
                unsigned b0 = *(const unsigned*)&Vt[(nt * 8 + gid) * 66 + kk + tig * 2];
                unsigned b1 = *(const unsigned*)&Vt[(nt * 8 + gid) * 66 + kk + tig * 2 + 8];
                MMA16(uc[nt][0], uc[nt][1], uc[nt][2], uc[nt][3], a0, a1, a2, a3, b0, b1);
            }
        }
        size_t ub = ((size_t)bh * 32 + c) * 4096;
        int d0 = wrow + gid;
#pragma unroll
        for (int nt = 0; nt < 8; nt++) {
            int e = nt * 8 + tig * 2;
            *(float2*)&g_U[ub + d0 * 64 + e] = make_float2(uc[nt][0], uc[nt][1]);
            *(float2*)&g_U[ub + (d0 + 8) * 64 + e] = make_float2(uc[nt][2], uc[nt][3]);
        }
    }
}

// ---------------- heb_state: chunk-level W recurrence (fp32) ----------------
__global__ void heb_state_kernel() {
    int bh = blockIdx.x;
    int b = bh >> 3;
    int t = threadIdx.x;
    float4 W[4];
#pragma unroll
    for (int j = 0; j < 4; j++) W[j] = make_float4(0.f, 0.f, 0.f, 0.f);
    for (int c = 0; c < 32; c++) {
        size_t off = ((size_t)bh * 32 + c) * 4096 + t * 16;
        float pl = g_Plast[b * 32 + c];
#pragma unroll
        for (int j = 0; j < 4; j++) {
            float4 u = *(const float4*)&g_U[off + j * 4];
            *(float4*)&g_Wst[off + j * 4] = W[j];
            W[j].x = pl * (W[j].x + ETA_C * u.x);
            W[j].y = pl * (W[j].y + ETA_C * u.y);
            W[j].z = pl * (W[j].z + ETA_C * u.z);
            W[j].w = pl * (W[j].w + ETA_C * u.w);
        }
    }
}

// ---------------- Hebbian inter: tensor-core O += Q·W ----------------
__global__ __launch_bounds__(128) void heb_inter_tc() {
    int bid = blockIdx.x;
    int c = bid & 31;
    int bh = bid >> 5;
    int h = bh & 7;
    int b = bh >> 3;
    int t0 = b * Nseq + c * 64;
    __shared__ __half Q[64 * 72];
    __shared__ __half Wt[64 * 66];
    int t = threadIdx.x;
    int warp = t >> 5, lane = t & 31;
    int gid = lane >> 2, tig = lane & 3;
    size_t wb = ((size_t)bh * 32 + c) * 4096;

    for (int idx = t; idx < 2048; idx += 128) {
        int i = idx >> 5, d2 = (idx & 31) * 2;
        *(unsigned*)&Q[i * 72 + d2] =
            *(const unsigned*)&g_qkvh[(size_t)(t0 + i) * 1536 + h * 64 + d2];
    }
    for (int idx = t; idx < 4096; idx += 128) {
        int d = idx >> 6, e = idx & 63;
        Wt[e * 66 + d] = __float2half(g_Wst[wb + idx]);
    }
    __syncthreads();

    int wrow = warp * 16;
    float oc[8][4];
    int i0 = t0 + wrow + gid;
#pragma unroll
    for (int nt = 0; nt < 8; nt++) {
        int col = h * 64 + nt * 8 + tig * 2;
        float2 p = __half22float2(*(const __half2*)&g_Oinh[(size_t)i0 * 512 + col]);
        float2 q = __half22float2(*(const __half2*)&g_Oinh[(size_t)(i0 + 8) * 512 + col]);
        oc[nt][0] = p.x; oc[nt][1] = p.y; oc[nt][2] = q.x; oc[nt][3] = q.y;
    }
#pragma unroll
    for (int kt = 0; kt < 4; kt++) {
        int kk = kt * 16;
        unsigned a0 = *(const unsigned*)&Q[(wrow + gid) * 72 + kk + tig * 2];
        unsigned a1 = *(const unsigned*)&Q[(wrow + gid + 8) * 72 + kk + tig * 2];
        unsigned a2 = *(const unsigned*)&Q[(wrow + gid) * 72 + kk + tig * 2 + 8];
        unsigned a3 = *(const unsigned*)&Q[(wrow + gid + 8) * 72 + kk + tig * 2 + 8];
#pragma unroll
        for (int nt = 0; nt < 8; nt++) {
            unsigned b0 = *(const unsigned*)&Wt[(nt * 8 + gid) * 66 + kk + tig * 2];
            unsigned b1 = *(const unsigned*)&Wt[(nt * 8 + gid) * 66 + kk + tig * 2 + 8];
            MMA16(oc[nt][0], oc[nt][1], oc[nt][2], oc[nt][3], a0, a1, a2, a3, b0, b1);
        }
    }
#pragma unroll
    for (int nt = 0; nt < 8; nt++) {
        int col = h * 64 + nt * 8 + tig * 2;
        __half2 p = __floats2half2_rn(oc[nt][0], oc[nt][1]);
        __half2 q = __floats2half2_rn(oc[nt][2], oc[nt][3]);
        *(unsigned*)&g_hebh[(size_t)i0 * 512 + col] = *(unsigned*)&p;
        *(unsigned*)&g_hebh[(size_t)(i0 + 8) * 512 + col] = *(unsigned*)&q;
    }
}

// ---------------- launch ----------------
extern "C" void kernel_launch(void* const* d_in, const int* in_sizes, int n_in,
                              void* d_out, int out_size) {
    const float* x     = (const float*)d_in[0];
    const float* ln1_g = (const float*)d_in[1];
    const float* ln1_b = (const float*)d_in[2];
    const float* ln2_g = (const float*)d_in[3];
    const float* ln2_b = (const float*)d_in[4];
    const float* ln3_g = (const float*)d_in[5];
    const float* ln3_b = (const float*)d_in[6];
    const float* w_pot = (const float*)d_in[7];
    const float* b_pot = (const float*)d_in[8];
    const float* w_bk  = (const float*)d_in[9];
    const float* b_bk  = (const float*)d_in[10];
    const float* w_qkv = (const float*)d_in[11];
    const float* b_qkv = (const float*)d_in[12];
    const float* w_out = (const float*)d_in[13];
    const float* b_out = (const float*)d_in[14];
    const float* w_ff1 = (const float*)d_in[15];
    const float* b_ff1 = (const float*)d_in[16];
    const float* w_ff2 = (const float*)d_in[17];
    const float* b_ff2 = (const float*)d_in[18];
    float* out = (float*)d_out;

    float *p_x1, *p_x2, *p_P, *p_Pinv;
    __half *p_qkvh, *p_xn2h, *p_xn3h, *p_hebh, *p_ffh, *p_wqt, *p_wot, *p_w1t, *p_w2t;
    cudaGetSymbolAddress((void**)&p_x1, g_x1);
    cudaGetSymbolAddress((void**)&p_x2, g_x2);
    cudaGetSymbolAddress((void**)&p_P, g_P);
    cudaGetSymbolAddress((void**)&p_Pinv, g_Pinv);
    cudaGetSymbolAddress((void**)&p_qkvh, g_qkvh);
    cudaGetSymbolAddress((void**)&p_xn2h, g_xn2h);
    cudaGetSymbolAddress((void**)&p_xn3h, g_xn3h);
    cudaGetSymbolAddress((void**)&p_hebh, g_hebh);
    cudaGetSymbolAddress((void**)&p_ffh, g_ffh);
    cudaGetSymbolAddress((void**)&p_wqt, g_wqt);
    cudaGetSymbolAddress((void**)&p_wot, g_wot);
    cudaGetSymbolAddress((void**)&p_w1t, g_w1t);
    cudaGetSymbolAddress((void**)&p_w2t, g_w2t);

    conv_wh_kernel<<<dim3(1536 / 32, 1024 / 32), 256>>>(w_qkv, p_wqt, 1024, 1536);
    conv_wh_kernel<<<dim3(1024 / 32, 512 / 32), 256>>>(w_out, p_wot, 512, 1024);
    conv_wh_kernel<<<dim3(4096 / 32, 1024 / 32), 256>>>(w_ff1, p_w1t, 1024, 4096);
    conv_wh_kernel<<<dim3(1024 / 32, 4096 / 32), 256>>>(w_ff2, p_w2t, 4096, 1024);

    ln1_pot_kernel<<<Ttok, 256>>>(x, ln1_g, ln1_b, w_pot, b_pot);
    pscan_kernel<<<128, 64>>>();
    bk_scan_kernel<<<8, 256>>>();
    bk_res_ln2_kernel<<<Ttok, 256>>>(x, w_bk, b_bk, ln2_g, ln2_b);
    h16_gemm<2><<<dim3(12, 64), 256>>>(p_xn2h, p_wqt, b_qkv, nullptr, p_P, p_Pinv, p_qkvh, Ttok,
                                       1536, 1024);
    heb_intra_tc<<<1024, 128>>>();
    heb_state_kernel<<<32, 256>>>();
    heb_inter_tc<<<1024, 128>>>();
    h16_gemm<0><<<dim3(8, 64), 256>>>(p_hebh, p_wot, b_out, p_x1, nullptr, nullptr, p_x2, Ttok,
                                      1024, 512);
    ln3_kernel<<<Ttok, 256>>>(ln3_g, ln3_b);
    h16_gemm<1><<<dim3(32, 64), 256>>>(p_xn3h, p_w1t, b_ff1, nullptr, nullptr, nullptr, p_ffh,
                                       Ttok, 4096, 1024);
    h16_gemm<0><<<dim3(8, 64), 256>>>(p_ffh, p_w2t, b_ff2, p_x2, nullptr, nullptr, out, Ttok,
                                      1024, 4096);
}

// round 16
// speedup vs baseline: 1.9377x; 1.0213x over previous
#include <cuda_runtime.h>
#include <cuda_fp16.h>
#include <stdint.h>
#include <math.h>

#define Bdim 4
#define Nseq 2048
#define Ddim 1024
#define FFd  4096
#define Ttok 8192
#define ETA_C 0.1f
#define DT_C  0.01f

// ---------------- scratch ----------------
__device__ float g_V[Ttok];
__device__ float g_gamma[Ttok];
__device__ float g_a[Ttok * 2];
__device__ float g_bcf[Ttok * 2];
__device__ float g_P[Ttok];
__device__ float g_Pinv[Ttok];
__device__ float g_Plast[Bdim * 32];
__device__ float g_x1[(size_t)Ttok * Ddim];
__device__ float g_x2[(size_t)Ttok * Ddim];
// fp16 buffers
__device__ __half g_Uh[32 * 32 * 4096];
__device__ __half g_Wsth[32 * 32 * 4096];
__device__ __half g_qkvh[(size_t)Ttok * 1536];   // [q*P | k/P | v]
__device__ __half g_Oinh[(size_t)Ttok * 512];
__device__ __half g_xn2h[(size_t)Ttok * Ddim];
__device__ __half g_xn3h[(size_t)Ttok * Ddim];
__device__ __half g_hebh[(size_t)Ttok * 512];
__device__ __half g_ffh[(size_t)Ttok * FFd];
// fp16 transposed weights [N][K]
__device__ __half g_wqt[(size_t)1536 * Ddim];
__device__ __half g_wot[(size_t)Ddim * 512];
__device__ __half g_w1t[(size_t)FFd * Ddim];
__device__ __half g_w2t[(size_t)Ddim * FFd];

// ---------------- helpers ----------------
__device__ __forceinline__ float blk_sum256(float v, float* sh) {
    int t = threadIdx.x;
#pragma unroll
    for (int o = 16; o > 0; o >>= 1) v += __shfl_down_sync(0xffffffffu, v, o);
    if ((t & 31) == 0) sh[t >> 5] = v;
    __syncthreads();
    if (t < 32) {
        float r = (t < 8) ? sh[t] : 0.f;
#pragma unroll
        for (int o = 4; o > 0; o >>= 1) r += __shfl_down_sync(0xffffffffu, r, o);
        if (t == 0) sh[0] = r;
    }
    __syncthreads();
    float r = sh[0];
    __syncthreads();
    return r;
}

__device__ __forceinline__ float gelu_f(float x) {
    float x3 = x * x * x;
    float u = 0.7978845608028654f * (x + 0.044715f * x3);
    return 0.5f * x * (1.f + tanhf(u));
}

#define MMA16(C0, C1, C2, C3, A0, A1, A2, A3, B0, B1)                                     \
    asm volatile(                                                                         \
        "mma.sync.aligned.m16n8k16.row.col.f32.f16.f16.f32 "                              \
        "{%0,%1,%2,%3}, {%4,%5,%6,%7}, {%8,%9}, {%0,%1,%2,%3};\n"                         \
        : "+f"(C0), "+f"(C1), "+f"(C2), "+f"(C3)                                          \
        : "r"(A0), "r"(A1), "r"(A2), "r"(A3), "r"(B0), "r"(B1))

// ---------------- fused weight transpose -> fp16 [N][K] (all 4 weights) ----------------
__global__ void conv_all_kernel(const float* __restrict__ w_qkv, const float* __restrict__ w_out,
                                const float* __restrict__ w_ff1,
                                const float* __restrict__ w_ff2) {
    __shared__ float tile[32][33];
    int blk = blockIdx.x;
    const float* W;
    __half* out;
    int K, N;
    if (blk < 1536) {
        W = w_qkv; out = g_wqt; K = 1024; N = 1536;
    } else if (blk < 2048) {
        blk -= 1536; W = w_out; out = g_wot; K = 512; N = 1024;
    } else if (blk < 6144) {
        blk -= 2048; W = w_ff1; out = g_w1t; K = 1024; N = 4096;
    } else {
        blk -= 6144; W = w_ff2; out = g_w2t; K = 4096; N = 1024;
    }
    int nTiles = N >> 5;
    int n0 = (blk % nTiles) * 32, k0 = (blk / nTiles) * 32;
    int t = threadIdx.x;
    int tx = t & 31, ty = t >> 5;
#pragma unroll
    for (int r = 0; r < 4; r++)
        tile[ty + r * 8][tx] = W[(size_t)(k0 + ty + r * 8) * N + n0 + tx];
    __syncthreads();
#pragma unroll
    for (int r = 0; r < 4; r++)
        out[(size_t)(n0 + ty + r * 8) * K + k0 + tx] = __float2half(tile[tx][ty + r * 8]);
}

// ---------------- K1: LN1 + potential ----------------
__global__ void ln1_pot_kernel(const float* __restrict__ x, const float* __restrict__ g1,
                               const float* __restrict__ b1, const float* __restrict__ wpot,
                               const float* __restrict__ bpot) {
    int row = blockIdx.x;
    int t = threadIdx.x;
    __shared__ float sh[8];
    const float4* xr = (const float4*)(x + (size_t)row * Ddim);
    float4 xv = xr[t];
    float s = xv.x + xv.y + xv.z + xv.w;
    float ss = xv.x * xv.x + xv.y * xv.y + xv.z * xv.z + xv.w * xv.w;
    s = blk_sum256(s, sh);
    ss = blk_sum256(ss, sh);
    float m = s * (1.f / Ddim);
    float var = ss * (1.f / Ddim) - m * m;
    float rstd = rsqrtf(var + 1e-5f);
    float xa[4] = {xv.x, xv.y, xv.z, xv.w};
    float p0 = 0.f, p1 = 0.f;
#pragma unroll
    for (int j = 0; j < 4; j++) {
        int col = t * 4 + j;
        float xn = (xa[j] - m) * rstd * g1[col] + b1[col];
        p0 += xn * wpot[col * 2];
        p1 += xn * wpot[col * 2 + 1];
    }
    p0 = blk_sum256(p0, sh);
    p1 = blk_sum256(p1, sh);
    if (t == 0) {
        g_V[row] = p0 + bpot[0];
        float z = p1 + bpot[1];
        float sp = (z > 20.f) ? z : log1pf(expf(z));
        g_gamma[row] = sp + 0.1f;
    }
}

// ---------------- P-scan ----------------
__global__ void pscan_kernel() {
    int b = blockIdx.x >> 5, c = blockIdx.x & 31;
    int t = threadIdx.x;  // 64
    int tok = b * Nseq + c * 64 + t;
    float v = g_gamma[tok] * DT_C;
    int lane = t & 31;
#pragma unroll
    for (int o = 1; o < 32; o <<= 1) {
        float n = __shfl_up_sync(0xffffffffu, v, o);
        if (lane >= o) v += n;
    }
    __shared__ float w0;
    if (t == 31) w0 = v;
    __syncthreads();
    if (t >= 32) v += w0;
    float P = expf(-v);
    g_P[tok] = P;
    g_Pinv[tok] = 1.f / P;
    if (t == 63) g_Plast[b * 32 + c] = P;
}

// ---------------- BK: parallel Mobius scan (fp64) ----------------
struct CM {
    double r00, i00, r01, i01, r10, i10, r11, i11;
};
__device__ __forceinline__ CM cm_mul(const CM& A, const CM& B) {
    CM C;
    C.r00 = A.r00 * B.r00 - A.i00 * B.i00 + A.r01 * B.r10 - A.i01 * B.i10;
    C.i00 = A.r00 * B.i00 + A.i00 * B.r00 + A.r01 * B.i10 + A.i01 * B.r10;
    C.r01 = A.r00 * B.r01 - A.i00 * B.i01 + A.r01 * B.r11 - A.i01 * B.i11;
    C.i01 = A.r00 * B.i01 + A.i00 * B.r01 + A.r01 * B.i11 + A.i01 * B.r11;
    C.r10 = A.r10 * B.r00 - A.i10 * B.i00 + A.r11 * B.r10 - A.i11 * B.i10;
    C.i10 = A.r10 * B.i00 + A.i10 * B.r00 + A.r11 * B.i10 + A.i11 * B.r10;
    C.r11 = A.r10 * B.r01 - A.i10 * B.i01 + A.r11 * B.r11 - A.i11 * B.i11;
    C.i11 = A.r10 * B.i01 + A.i10 * B.r01 + A.r11 * B.i11 + A.i11 * B.r11;
    return C;
}
__device__ __forceinline__ void cm_norm(CM& A) {
    double m = fabs(A.r00);
    m = fmax(m, fabs(A.i00)); m = fmax(m, fabs(A.r01)); m = fmax(m, fabs(A.i01));
    m = fmax(m, fabs(A.r10)); m = fmax(m, fabs(A.i10)); m = fmax(m, fabs(A.r11));
    m = fmax(m, fabs(A.i11));
    double s = 1.0 / m;
    A.r00 *= s; A.i00 *= s; A.r01 *= s; A.i01 *= s;
    A.r10 *= s; A.i10 *= s; A.r11 *= s; A.i11 *= s;
}

__global__ void bk_scan_kernel() {
    int bb = blockIdx.x >> 1;
    int dir = blockIdx.x & 1;
    int t = threadIdx.x;
    float* out = dir ? g_bcf : g_a;
    __shared__ CM sm[256];

    double dr[8], di[8];
    CM L;
    L.r00 = 1; L.i00 = 0; L.r01 = 0; L.i01 = 0;
    L.r10 = 0; L.i10 = 0; L.r11 = 1; L.i11 = 0;
#pragma unroll
    for (int u = 0; u < 8; u++) {
        int j = t * 8 + u;
        int pos = dir ? (Nseq - 1 - j) : j;
        int gi = bb * Nseq + pos;
        dr[u] = (double)g_V[gi] + 2.0;
        di[u] = -(double)g_gamma[gi];
        CM Nw;
        Nw.r00 = dr[u] * L.r00 - di[u] * L.i00 - L.r10;
        Nw.i00 = dr[u] * L.i00 + di[u] * L.r00 - L.i10;
        Nw.r01 = dr[u] * L.r01 - di[u] * L.i01 - L.r11;
        Nw.i01 = dr[u] * L.i01 + di[u] * L.r01 - L.i11;
        Nw.r10 = L.r00; Nw.i10 = L.i00;
        Nw.r11 = L.r01; Nw.i11 = L.i01;
        L = Nw;
    }
    cm_norm(L);
    sm[t] = L;
    __syncthreads();
    for (int off = 1; off < 256; off <<= 1) {
        CM Pm;
        bool act = (t >= off);
        if (act) Pm = sm[t - off];
        __syncthreads();
        if (act) {
            L = cm_mul(L, Pm);
            cm_norm(L);
            sm[t] = L;
        }
        __syncthreads();
    }
    double pr, pi, qr, qi;
    if (t == 0) {
        pr = 1; pi = 0; qr = 0; qi = 0;
    } else {
        CM E = sm[t - 1];
        pr = E.r00; pi = E.i00; qr = E.r10; qi = E.i10;
    }
#pragma unroll
    for (int u = 0; u < 8; u++) {
        int j = t * 8 + u;
        int pos = dir ? (Nseq - 1 - j) : j;
        int gi = bb * Nseq + pos;
        double npr = dr[u] * pr - di[u] * pi - qr;
        double npi = dr[u] * pi + di[u] * pr - qi;
        qr = pr; qi = pi; pr = npr; pi = npi;
        double m = fmax(fmax(fabs(pr), fabs(pi)), fmax(fabs(qr), fabs(qi)));
        double sc = 1.0 / m;
        pr *= sc; pi *= sc; qr *= sc; qi *= sc;
        double den = 1.0 / (qr * qr + qi * qi);
        out[gi * 2] = (float)((pr * qr + pi * qi) * den);
        out[gi * 2 + 1] = (float)((pi * qr - pr * qi) * den);
    }
}

// ---------------- K3: BK + residual + LN2 -> fp16 ----------------
__global__ void bk_res_ln2_kernel(const float* __restrict__ x, const float* __restrict__ wbk,
                                  const float* __restrict__ bbk, const float* __restrict__ g2,
                                  const float* __restrict__ b2) {
    int row = blockIdx.x;
    int t = threadIdx.x;
    __shared__ float sh[8];
    __shared__ float f01[2];
    if (t == 0) {
        float are = g_a[row * 2], aim = g_a[row * 2 + 1];
        float bre = g_bcf[row * 2], bim = g_bcf[row * 2 + 1];
        float drr = g_V[row] + 2.f, dii = -g_gamma[row];
        float nr = are + bre - drr, ni = aim + bim - dii;
        float inv = 1.f / (nr * nr + ni * ni);
        f01[0] = nr * inv;
        f01[1] = -ni * inv;
    }
    __syncthreads();
    float f0 = f01[0], f1 = f01[1];
    size_t base = (size_t)row * Ddim;
    float y[4];
    float s = 0.f, ss = 0.f;
#pragma unroll
    for (int j = 0; j < 4; j++) {
        int col = t * 4 + j;
        float v = x[base + col] + f0 * wbk[col] + f1 * wbk[Ddim + col] + bbk[col];
        y[j] = v;
        s += v;
        ss += v * v;
        g_x1[base + col] = v;
    }
    s = blk_sum256(s, sh);
    ss = blk_sum256(ss, sh);
    float m = s * (1.f / Ddim);
    float var = ss * (1.f / Ddim) - m * m;
    float rstd = rsqrtf(var + 1e-5f);
    __half2 h2[2];
#pragma unroll
    for (int j = 0; j < 2; j++) {
        float v0 = (y[2 * j] - m) * rstd * g2[t * 4 + 2 * j] + b2[t * 4 + 2 * j];
        float v1 = (y[2 * j + 1] - m) * rstd * g2[t * 4 + 2 * j + 1] + b2[t * 4 + 2 * j + 1];
        h2[j] = __floats2half2_rn(v0, v1);
    }
    *(uint2*)&g_xn2h[base + t * 4] = make_uint2(*(unsigned*)&h2[0], *(unsigned*)&h2[1]);
}

// ---------------- LN3 -> fp16 ----------------
__global__ void ln3_kernel(const float* __restrict__ g3, const float* __restrict__ b3) {
    int row = blockIdx.x;
    int t = threadIdx.x;
    __shared__ float sh[8];
    size_t base = (size_t)row * Ddim;
    float4 xv = *(const float4*)&g_x2[base + t * 4];
    float s = xv.x + xv.y + xv.z + xv.w;
    float ss = xv.x * xv.x + xv.y * xv.y + xv.z * xv.z + xv.w * xv.w;
    s = blk_sum256(s, sh);
    ss = blk_sum256(ss, sh);
    float m = s * (1.f / Ddim);
    float var = ss * (1.f / Ddim) - m * m;
    float rstd = rsqrtf(var + 1e-5f);
    float xa[4] = {xv.x, xv.y, xv.z, xv.w};
    __half2 h2[2];
#pragma unroll
    for (int j = 0; j < 2; j++) {
        float v0 = (xa[2 * j] - m) * rstd * g3[t * 4 + 2 * j] + b3[t * 4 + 2 * j];
        float v1 = (xa[2 * j + 1] - m) * rstd * g3[t * 4 + 2 * j + 1] + b3[t * 4 + 2 * j + 1];
        h2[j] = __floats2half2_rn(v0, v1);
    }
    *(uint2*)&g_xn3h[base + t * 4] = make_uint2(*(unsigned*)&h2[0], *(unsigned*)&h2[1]);
}

// ---------------- FP16 tensor GEMM: 128x128, 8 warps, K-step 32 ----------------
#define HST 40

__device__ __forceinline__ void cpa16(unsigned dst, const void* src) {
    asm volatile("cp.async.ca.shared.global [%0], [%1], 16;\n" ::"r"(dst), "l"(src));
}

// EPI: 0 = fp32 out (+Rd); 1 = gelu -> fp16; 2 = qkv scale -> fp16
template <int EPI>
__global__ __launch_bounds__(256, 2) void h16_gemm(const __half* __restrict__ A,
                                                   const __half* __restrict__ Bt,
                                                   const float* __restrict__ bias,
                                                   const float* __restrict__ Rd,
                                                   const float* __restrict__ Pv,
                                                   const float* __restrict__ Pinv,
                                                   void* __restrict__ Cv, int M, int N, int K) {
    __shared__ __half As[2][128 * HST];
    __shared__ __half Bs[2][128 * HST];
    int t = threadIdx.x;
    int warp = t >> 5, lane = t & 31;
    int gid = lane >> 2, tig = lane & 3;
    int m0 = blockIdx.y * 128, n0 = blockIdx.x * 128;
    int wm = (warp >> 2) * 64, wn = (warp & 3) * 32;

    float acc[4][4][4];
#pragma unroll
    for (int i = 0; i < 4; i++)
#pragma unroll
        for (int j = 0; j < 4; j++)
#pragma unroll
            for (int r = 0; r < 4; r++) acc[i][j][r] = 0.f;

    unsigned aBase = (unsigned)__cvta_generic_to_shared(&As[0][0]);
    unsigned bBase = (unsigned)__cvta_generic_to_shared(&Bs[0][0]);
    int r0 = t >> 2, kc0 = (t & 3) * 8;
    int r1 = (t + 256) >> 2, kc1 = ((t + 256) & 3) * 8;
    unsigned aD0 = aBase + (unsigned)(r0 * HST + kc0) * 2u;
    unsigned aD1 = aBase + (unsigned)(r1 * HST + kc1) * 2u;
    unsigned bD0 = bBase + (unsigned)(r0 * HST + kc0) * 2u;
    unsigned bD1 = bBase + (unsigned)(r1 * HST + kc1) * 2u;
    const __half* Ag0 = A + (size_t)(m0 + r0) * K + kc0;
    const __half* Ag1 = A + (size_t)(m0 + r1) * K + kc1;
    const __half* Bg0 = Bt + (size_t)(n0 + r0) * K + kc0;
    const __half* Bg1 = Bt + (size_t)(n0 + r1) * K + kc1;
    const unsigned SOFF = (unsigned)(128 * HST) * 2u;

    const int KT = K >> 5;

#define HFILL(J)                                \
    {                                           \
        int _j = (J);                           \
        unsigned so = (_j & 1) ? SOFF : 0u;     \
        int ko = _j << 5;                       \
        cpa16(aD0 + so, Ag0 + ko);              \
        cpa16(aD1 + so, Ag1 + ko);              \
        cpa16(bD0 + so, Bg0 + ko);              \
        cpa16(bD1 + so, Bg1 + ko);              \
        asm volatile("cp.async.commit_group;"); \
    }

    HFILL(0);

    for (int kt = 0; kt < KT; kt++) {
        if (kt + 1 < KT) {
            HFILL(kt + 1);
            asm volatile("cp.async.wait_group 1;");
        } else {
            asm volatile("cp.async.wait_group 0;");
        }
        __syncthreads();
        const __half* as = &As[kt & 1][0];
        const __half* bs = &Bs[kt & 1][0];
#pragma unroll
        for (int kk = 0; kk < 32; kk += 16) {
            unsigned af[4][4], bf[4][2];
#pragma unroll
            for (int mt = 0; mt < 4; mt++) {
                int rb = wm + mt * 16 + gid;
                af[mt][0] = *(const unsigned*)(as + rb * HST + kk + tig * 2);
                af[mt][1] = *(const unsigned*)(as + (rb + 8) * HST + kk + tig * 2);
                af[mt][2] = *(const unsigned*)(as + rb * HST + kk + tig * 2 + 8);
                af[mt][3] = *(const unsigned*)(as + (rb + 8) * HST + kk + tig * 2 + 8);
            }
#pragma unroll
            for (int nt = 0; nt < 4; nt++) {
                int cb = wn + nt * 8 + gid;
                bf[nt][0] = *(const unsigned*)(bs + cb * HST + kk + tig * 2);
                bf[nt][1] = *(const unsigned*)(bs + cb * HST + kk + tig * 2 + 8);
            }
#pragma unroll
            for (int mt = 0; mt < 4; mt++)
#pragma unroll
                for (int nt = 0; nt < 4; nt++)
                    MMA16(acc[mt][nt][0], acc[mt][nt][1], acc[mt][nt][2], acc[mt][nt][3],
                          af[mt][0], af[mt][1], af[mt][2], af[mt][3], bf[nt][0], bf[nt][1]);
        }
        __syncthreads();
    }

#pragma unroll
    for (int mt = 0; mt < 4; mt++) {
        int row = m0 + wm + mt * 16 + gid;
        float sP0 = 0.f, sPi0 = 0.f, sP8 = 0.f, sPi8 = 0.f;
        if (EPI == 2) {
            sP0 = Pv[row]; sPi0 = Pinv[row];
            sP8 = Pv[row + 8]; sPi8 = Pinv[row + 8];
        }
#pragma unroll
        for (int nt = 0; nt < 4; nt++) {
            int col = n0 + wn + nt * 8 + tig * 2;
            float b0 = bias[col], b1 = bias[col + 1];
            float v0 = acc[mt][nt][0] + b0;
            float v1 = acc[mt][nt][1] + b1;
            float v2 = acc[mt][nt][2] + b0;
            float v3 = acc[mt][nt][3] + b1;
            if (EPI == 1) {
                v0 = gelu_f(v0); v1 = gelu_f(v1); v2 = gelu_f(v2); v3 = gelu_f(v3);
                __half* C = (__half*)Cv;
                __half2 p = __floats2half2_rn(v0, v1);
                __half2 q = __floats2half2_rn(v2, v3);
                *(unsigned*)&C[(size_t)row * N + col] = *(unsigned*)&p;
                *(unsigned*)&C[(size_t)(row + 8) * N + col] = *(unsigned*)&q;
            } else if (EPI == 2) {
                float s0 = (col < 512) ? sP0 : ((col < 1024) ? sPi0 : 1.f);
                float s8 = (col < 512) ? sP8 : ((col < 1024) ? sPi8 : 1.f);
                __half* C = (__half*)Cv;
                __half2 p = __floats2half2_rn(v0 * s0, v1 * s0);
                __half2 q = __floats2half2_rn(v2 * s8, v3 * s8);
                *(unsigned*)&C[(size_t)row * N + col] = *(unsigned*)&p;
                *(unsigned*)&C[(size_t)(row + 8) * N + col] = *(unsigned*)&q;
            } else {
                float* C = (float*)Cv;
                size_t o0 = (size_t)row * N + col;
                size_t o2 = (size_t)(row + 8) * N + col;
                if (Rd != nullptr) {
                    float2 rr0 = *(const float2*)&Rd[o0];
                    float2 rr2 = *(const float2*)&Rd[o2];
                    v0 += rr0.x; v1 += rr0.y; v2 += rr2.x; v3 += rr2.y;
                }
                *(float2*)&C[o0] = make_float2(v0, v1);
                *(float2*)&C[o2] = make_float2(v2, v3);
            }
        }
    }
}

// ---------------- Hebbian intra: tensor-core S/O/U ----------------
__global__ __launch_bounds__(128) void heb_intra_tc() {
    int bid = blockIdx.x;
    int c = bid & 31;
    int bh = bid >> 5;
    int h = bh & 7;
    int b = bh >> 3;
    int t0 = b * Nseq + c * 64;
    __shared__ __half Q[64 * 72];
    __shared__ __half K[64 * 72];
    __shared__ __half Kt[64 * 66];
    __shared__ __half Vt[64 * 66];
    int t = threadIdx.x;
    int warp = t >> 5, lane = t & 31;
    int gid = lane >> 2, tig = lane & 3;

    for (int idx = t; idx < 2048; idx += 128) {
        int i = idx >> 5, d2 = (idx & 31) * 2;
        size_t qb = (size_t)(t0 + i) * 1536 + h * 64 + d2;
        *(unsigned*)&Q[i * 72 + d2] = *(const unsigned*)&g_qkvh[qb];
        __half2 kh = *(const __half2*)&g_qkvh[qb + 512];
        *(__half2*)&K[i * 72 + d2] = kh;
        Kt[d2 * 66 + i] = __low2half(kh);
        Kt[(d2 + 1) * 66 + i] = __high2half(kh);
        __half2 vh = *(const __half2*)&g_qkvh[qb + 1024];
        Vt[d2 * 66 + i] = __low2half(vh);
        Vt[(d2 + 1) * 66 + i] = __high2half(vh);
    }
    __syncthreads();

    int wrow = warp * 16;

    // ---- S = Q·K^T ----
    float sc[8][4];
#pragma unroll
    for (int nt = 0; nt < 8; nt++)
#pragma unroll
        for (int r = 0; r < 4; r++) sc[nt][r] = 0.f;
#pragma unroll
    for (int kt = 0; kt < 4; kt++) {
        int kk = kt * 16;
        unsigned a0 = *(const unsigned*)&Q[(wrow + gid) * 72 + kk + tig * 2];
        unsigned a1 = *(const unsigned*)&Q[(wrow + gid + 8) * 72 + kk + tig * 2];
        unsigned a2 = *(const unsigned*)&Q[(wrow + gid) * 72 + kk + tig * 2 + 8];
        unsigned a3 = *(const unsigned*)&Q[(wrow + gid + 8) * 72 + kk + tig * 2 + 8];
#pragma unroll
        for (int nt = 0; nt < 8; nt++) {
            unsigned b0 = *(const unsigned*)&K[(nt * 8 + gid) * 72 + kk + tig * 2];
            unsigned b1 = *(const unsigned*)&K[(nt * 8 + gid) * 72 + kk + tig * 2 + 8];
            MMA16(sc[nt][0], sc[nt][1], sc[nt][2], sc[nt][3], a0, a1, a2, a3, b0, b1);
        }
    }
    unsigned apk[8][2];
    {
        int i0 = wrow + gid, i8 = i0 + 8;
#pragma unroll
        for (int nt = 0; nt < 8; nt++) {
            int s0 = nt * 8 + tig * 2;
            float v0 = (s0 <= i0) ? ETA_C * sc[nt][0] : 0.f;
            float v1 = (s0 + 1 <= i0) ? ETA_C * sc[nt][1] : 0.f;
            float v2 = (s0 <= i8) ? ETA_C * sc[nt][2] : 0.f;
            float v3 = (s0 + 1 <= i8) ? ETA_C * sc[nt][3] : 0.f;
            __half2 p = __floats2half2_rn(v0, v1);
            __half2 q = __floats2half2_rn(v2, v3);
            apk[nt][0] = *(unsigned*)&p;
            apk[nt][1] = *(unsigned*)&q;
        }
    }
    // ---- O = S·V ----
    {
        float oc[8][4];
#pragma unroll
        for (int nt = 0; nt < 8; nt++)
#pragma unroll
            for (int r = 0; r < 4; r++) oc[nt][r] = 0.f;
#pragma unroll
        for (int kt = 0; kt < 4; kt++) {
            int kk = kt * 16;
            unsigned a0 = apk[2 * kt][0], a1 = apk[2 * kt][1];
            unsigned a2 = apk[2 * kt + 1][0], a3 = apk[2 * kt + 1][1];
#pragma unroll
            for (int nt = 0; nt < 8; nt++) {
                unsigned b0 = *(const unsigned*)&Vt[(nt * 8 + gid) * 66 + kk + tig * 2];
                unsigned b1 = *(const unsigned*)&Vt[(nt * 8 + gid) * 66 + kk + tig * 2 + 8];
                MMA16(oc[nt][0], oc[nt][1], oc[nt][2], oc[nt][3], a0, a1, a2, a3, b0, b1);
            }
        }
        int i0 = t0 + wrow + gid;
#pragma unroll
        for (int nt = 0; nt < 8; nt++) {
            int col = h * 64 + nt * 8 + tig * 2;
            __half2 p = __floats2half2_rn(oc[nt][0], oc[nt][1]);
            __half2 q = __floats2half2_rn(oc[nt][2], oc[nt][3]);
            *(unsigned*)&g_Oinh[(size_t)i0 * 512 + col] = *(unsigned*)&p;
            *(unsigned*)&g_Oinh[(size_t)(i0 + 8) * 512 + col] = *(unsigned*)&q;
        }
    }
    // ---- U = K^T·V -> fp16 ----
    {
        float uc[8][4];
#pragma unroll
        for (int nt = 0; nt < 8; nt++)
#pragma unroll
            for (int r = 0; r < 4; r++) uc[nt][r] = 0.f;
#pragma unroll
        for (int kt = 0; kt < 4; kt++) {
            int kk = kt * 16;
            unsigned a0 = *(const unsigned*)&Kt[(wrow + gid) * 66 + kk + tig * 2];
            unsigned a1 = *(const unsigned*)&Kt[(wrow + gid + 8) * 66 + kk + tig * 2];
            unsigned a2 = *(const unsigned*)&Kt[(wrow + gid) * 66 + kk + tig * 2 + 8];
            unsigned a3 = *(const unsigned*)&Kt[(wrow + gid + 8) * 66 + kk + tig * 2 + 8];
#pragma unroll
            for (int nt = 0; nt < 8; nt++) {
                unsigned b0 = *(const unsigned*)&Vt[(nt * 8 + gid) * 66 + kk + tig * 2];
                unsigned b1 = *(const unsigned*)&Vt[(nt * 8 + gid) * 66 + kk + tig * 2 + 8];
                MMA16(uc[nt][0], uc[nt][1], uc[nt][2], uc[nt][3], a0, a1, a2, a3, b0, b1);
            }
        }
        size_t ub = ((size_t)bh * 32 + c) * 4096;
        int d0 = wrow + gid;
#pragma unroll
        for (int nt = 0; nt < 8; nt++) {
            int e = nt * 8 + tig * 2;
            __half2 u0 = __floats2half2_rn(uc[nt][0], uc[nt][1]);
            __half2 u1 = __floats2half2_rn(uc[nt][2], uc[nt][3]);
            *(unsigned*)&g_Uh[ub + d0 * 64 + e] = *(unsigned*)&u0;
            *(unsigned*)&g_Uh[ub + (d0 + 8) * 64 + e] = *(unsigned*)&u1;
        }
    }
}

// ---------------- heb_state: parallel per-element recurrence (fp16 io, fp32 math) ----------------
__global__ void heb_state_kernel() {
    int g = blockIdx.x * 128 + threadIdx.x;  // 32768 threads
    int bh = g >> 10, grp = g & 1023;
    int b = bh >> 3;
    float4 W = make_float4(0.f, 0.f, 0.f, 0.f);
    size_t base = (size_t)bh * 32 * 4096 + grp * 4;
    for (int c = 0; c < 32; c++) {
        size_t off = base + (size_t)c * 4096;
        uint2 up = *(const uint2*)&g_Uh[off];
        __half2 w0 = __floats2half2_rn(W.x, W.y);
        __half2 w1 = __floats2half2_rn(W.z, W.w);
        *(uint2*)&g_Wsth[off] = make_uint2(*(unsigned*)&w0, *(unsigned*)&w1);
        float pl = g_Plast[b * 32 + c];
        float2 u0 = __half22float2(*(__half2*)&up.x);
        float2 u1 = __half22float2(*(__half2*)&up.y);
        W.x = pl * (W.x + ETA_C * u0.x);
        W.y = pl * (W.y + ETA_C * u0.y);
        W.z = pl * (W.z + ETA_C * u1.x);
        W.w = pl * (W.w + ETA_C * u1.y);
    }
}

// ---------------- Hebbian inter: tensor-core O += Q·W ----------------
__global__ __launch_bounds__(128) void heb_inter_tc() {
    int bid = blockIdx.x;
    int c = bid & 31;
    int bh = bid >> 5;
    int h = bh & 7;
    int b = bh >> 3;
    int t0 = b * Nseq + c * 64;
    __shared__ __half Q[64 * 72];
    __shared__ __half Wt[64 * 66];
    int t = threadIdx.x;
    int warp = t >> 5, lane = t & 31;
    int gid = lane >> 2, tig = lane & 3;
    size_t wb = ((size_t)bh * 32 + c) * 4096;

    for (int idx = t; idx < 2048; idx += 128) {
        int i = idx >> 5, d2 = (idx & 31) * 2;
        *(unsigned*)&Q[i * 72 + d2] =
            *(const unsigned*)&g_qkvh[(size_t)(t0 + i) * 1536 + h * 64 + d2];
    }
    for (int idx = t; idx < 2048; idx += 128) {
        int d = idx >> 5, e2 = (idx & 31) * 2;
        __half2 w = *(const __half2*)&g_Wsth[wb + d * 64 + e2];
        Wt[e2 * 66 + d] = __low2half(w);
        Wt[(e2 + 1) * 66 + d] = __high2half(w);
    }
    __syncthreads();

    int wrow = warp * 16;
    float oc[8][4];
    int i0 = t0 + wrow + gid;
#pragma unroll
    for (int nt = 0; nt < 8; nt++) {
        int col = h * 64 + nt * 8 + tig * 2;
        float2 p = __half22float2(*(const __half2*)&g_Oinh[(size_t)i0 * 512 + col]);
        float2 q = __half22float2(*(const __half2*)&g_Oinh[(size_t)(i0 + 8) * 512 + col]);
        oc[nt][0] = p.x; oc[nt][1] = p.y; oc[nt][2] = q.x; oc[nt][3] = q.y;
    }
#pragma unroll
    for (int kt = 0; kt < 4; kt++) {
        int kk = kt * 16;
        unsigned a0 = *(const unsigned*)&Q[(wrow + gid) * 72 + kk + tig * 2];
        unsigned a1 = *(const unsigned*)&Q[(wrow + gid + 8) * 72 + kk + tig * 2];
        unsigned a2 = *(const unsigned*)&Q[(wrow + gid) * 72 + kk + tig * 2 + 8];
        unsigned a3 = *(const unsigned*)&Q[(wrow + gid + 8) * 72 + kk + tig * 2 + 8];
#pragma unroll
        for (int nt = 0; nt < 8; nt++) {
            unsigned b0 = *(const unsigned*)&Wt[(nt * 8 + gid) * 66 + kk + tig * 2];
            unsigned b1 = *(const unsigned*)&Wt[(nt * 8 + gid) * 66 + kk + tig * 2 + 8];
            MMA16(oc[nt][0], oc[nt][1], oc[nt][2], oc[nt][3], a0, a1, a2, a3, b0, b1);
        }
    }
#pragma unroll
    for (int nt = 0; nt < 8; nt++) {
        int col = h * 64 + nt * 8 + tig * 2;
        __half2 p = __floats2half2_rn(oc[nt][0], oc[nt][1]);
        __half2 q = __floats2half2_rn(oc[nt][2], oc[nt][3]);
        *(unsigned*)&g_hebh[(size_t)i0 * 512 + col] = *(unsigned*)&p;
        *(unsigned*)&g_hebh[(size_t)(i0 + 8) * 512 + col] = *(unsigned*)&q;
    }
}

// ---------------- launch ----------------
extern "C" void kernel_launch(void* const* d_in, const int* in_sizes, int n_in,
                              void* d_out, int out_size) {
    const float* x     = (const float*)d_in[0];
    const float* ln1_g = (const float*)d_in[1];
    const float* ln1_b = (const float*)d_in[2];
    const float* ln2_g = (const float*)d_in[3];
    const float* ln2_b = (const float*)d_in[4];
    const float* ln3_g = (const float*)d_in[5];
    const float* ln3_b = (const float*)d_in[6];
    const float* w_pot = (const float*)d_in[7];
    const float* b_pot = (const float*)d_in[8];
    const float* w_bk  = (const float*)d_in[9];
    const float* b_bk  = (const float*)d_in[10];
    const float* w_qkv = (const float*)d_in[11];
    const float* b_qkv = (const float*)d_in[12];
    const float* w_out = (const float*)d_in[13];
    const float* b_out = (const float*)d_in[14];
    const float* w_ff1 = (const float*)d_in[15];
    const float* b_ff1 = (const float*)d_in[16];
    const float* w_ff2 = (const float*)d_in[17];
    const float* b_ff2 = (const float*)d_in[18];
    float* out = (float*)d_out;

    float *p_x1, *p_x2, *p_P, *p_Pinv;
    __half *p_qkvh, *p_xn2h, *p_xn3h, *p_hebh, *p_ffh, *p_wqt, *p_wot, *p_w1t, *p_w2t;
    cudaGetSymbolAddress((void**)&p_x1, g_x1);
    cudaGetSymbolAddress((void**)&p_x2, g_x2);
    cudaGetSymbolAddress((void**)&p_P, g_P);
    cudaGetSymbolAddress((void**)&p_Pinv, g_Pinv);
    cudaGetSymbolAddress((void**)&p_qkvh, g_qkvh);
    cudaGetSymbolAddress((void**)&p_xn2h, g_xn2h);
    cudaGetSymbolAddress((void**)&p_xn3h, g_xn3h);
    cudaGetSymbolAddress((void**)&p_hebh, g_hebh);
    cudaGetSymbolAddress((void**)&p_ffh, g_ffh);
    cudaGetSymbolAddress((void**)&p_wqt, g_wqt);
    cudaGetSymbolAddress((void**)&p_wot, g_wot);
    cudaGetSymbolAddress((void**)&p_w1t, g_w1t);
    cudaGetSymbolAddress((void**)&p_w2t, g_w2t);

    conv_all_kernel<<<10240, 256>>>(w_qkv, w_out, w_ff1, w_ff2);

    ln1_pot_kernel<<<Ttok, 256>>>(x, ln1_g, ln1_b, w_pot, b_pot);
    pscan_kernel<<<128, 64>>>();
    bk_scan_kernel<<<8, 256>>>();
    bk_res_ln2_kernel<<<Ttok, 256>>>(x, w_bk, b_bk, ln2_g, ln2_b);
    h16_gemm<2><<<dim3(12, 64), 256>>>(p_xn2h, p_wqt, b_qkv, nullptr, p_P, p_Pinv, p_qkvh, Ttok,
                                       1536, 1024);
    heb_intra_tc<<<1024, 128>>>();
    heb_state_kernel<<<256, 128>>>();
    heb_inter_tc<<<1024, 128>>>();
    h16_gemm<0><<<dim3(8, 64), 256>>>(p_hebh, p_wot, b_out, p_x1, nullptr, nullptr, p_x2, Ttok,
                                      1024, 512);
    ln3_kernel<<<Ttok, 256>>>(ln3_g, ln3_b);
    h16_gemm<1><<<dim3(32, 64), 256>>>(p_xn3h, p_w1t, b_ff1, nullptr, nullptr, nullptr, p_ffh,
                                       Ttok, 4096, 1024);
    h16_gemm<0><<<dim3(8, 64), 256>>>(p_ffh, p_w2t, b_ff2, p_x2, nullptr, nullptr, out, Ttok,
                                      1024, 4096);
}